// round 11
// baseline (speedup 1.0000x reference)
#include <cuda_runtime.h>
#include <cuda_bf16.h>
#include <cuda_fp16.h>
#include <cstdint>

typedef unsigned long long ull;

#define NN 50000
#define EE 1600000
#define ETOT 1650000
#define KH 4
#define DHH 64
#define DXX 128
#define CC 256          // KH*DHH
#define NEG 0.01f
#define SCB 49          // scan blocks (49*1024 >= NN)
#define LOG2E 1.44269504f

// f1: blocks [0,782) = wx tiles, [782, 782+3125) = hist
#define F1_WX 782
#define F1_HIST 3125
// f2: blocks [0,3321) = scatter, [3321, 3321+6250) = scores
#define F2_SCAT 3321
#define F2_SCORE 6250

// ---------------- scratch (static device globals; zero-init at load) --------
__device__ uint2 g_Wxf8[NN * 32];        // 12.8 MB  fp8 Wx[n][c] (256B/row)
__device__ uint4 g_aggh4[NN * 32];       // 25.6 MB  bf16 E = exp(agg)
__device__ float g_sif[NN * KH];         // (si + ab) * log2e, per head
__device__ float g_sjf[NN * KH];         // sj * log2e, per head
__device__ int g_cnt[NN];                // zero-init; re-zeroed by scan1
__device__ int g_rowptr[NN + 1];
__device__ int g_cur[NN];
__device__ int g_bsum[64];
__device__ int g_csr[ETOT];              // src indices grouped by dst
__device__ float g_colsum[CC];           // re-zeroed by scan2

// ---------------- helpers ---------------------------------------------------
__device__ __forceinline__ float bflo(unsigned u) { return __uint_as_float(u << 16); }
__device__ __forceinline__ float bfhi(unsigned u) { return __uint_as_float(u & 0xffff0000u); }
__device__ __forceinline__ int clampi(int v) {
    return v < 0 ? 0 : (v >= NN ? NN - 1 : v);
}

#define PACKBF(r, lo, hi) asm("cvt.rn.bf16x2.f32 %0, %1, %2;" : "=r"(r) : "f"(hi), "f"(lo))
#define PACKF8(r, lo, hi) \
    asm("cvt.rn.satfinite.e4m3x2.f32 %0, %1, %2;" : "=h"(r) : "f"(hi), "f"(lo))
#define UNPF8(d, s) asm("cvt.rn.f16x2.e4m3x2 %0, %1;" : "=r"(d) : "h"(s))
#define EX2A(d, s) asm("ex2.approx.ftz.f32 %0, %1;" : "=f"(d) : "f"(s))

__device__ __forceinline__ void f8_to_f16x2(unsigned u32v, __half2& lo, __half2& hi) {
    unsigned short sl = (unsigned short)(u32v & 0xffffu);
    unsigned short sh = (unsigned short)(u32v >> 16);
    unsigned a, b;
    UNPF8(a, sl);
    UNPF8(b, sh);
    lo = *(__half2*)&a;
    hi = *(__half2*)&b;
}

#define LDSM4(r0, r1, r2, r3, a) asm volatile( \
    "ldmatrix.sync.aligned.m8n8.x4.shared.b16 {%0,%1,%2,%3}, [%4];" \
    : "=r"(r0), "=r"(r1), "=r"(r2), "=r"(r3) : "r"(a))
#define LDSM2(r0, r1, a) asm volatile( \
    "ldmatrix.sync.aligned.m8n8.x2.shared.b16 {%0,%1}, [%2];" \
    : "=r"(r0), "=r"(r1) : "r"(a))
#define MMA16816(d, a, b) asm volatile( \
    "mma.sync.aligned.m16n8k16.row.col.f32.bf16.bf16.f32 " \
    "{%0,%1,%2,%3}, {%4,%5,%6,%7}, {%8,%9}, {%0,%1,%2,%3};" \
    : "+f"((d)[0]), "+f"((d)[1]), "+f"((d)[2]), "+f"((d)[3]) \
    : "r"((a)[0]), "r"((a)[1]), "r"((a)[2]), "r"((a)[3]), "r"((b)[0]), "r"((b)[1]))

__device__ __forceinline__ unsigned pack_bf2(float lo, float hi) {
    unsigned r; PACKBF(r, lo, hi); return r;
}

// ---------------- F1: Wx GEMM (bf16 mma.sync, fp8 out) ∥ degree hist -------
__global__ __launch_bounds__(256) void k_f1(const float* __restrict__ x,
                                            const float* __restrict__ Ww,
                                            const float* __restrict__ Wb,
                                            const int* __restrict__ ei) {
    __shared__ __align__(16) char smbuf[36864];
    __shared__ float biasS[128];
    int tid = threadIdx.x, lane = tid & 31, wid = tid >> 5;

    if (blockIdx.x >= F1_WX) {
        int i = (blockIdx.x - F1_WX) * 256 + tid;
        if (i < EE / 2) {
            int2 d2 = *(const int2*)&ei[EE + 2 * i];
            atomicAdd(&g_cnt[clampi(d2.x)], 1);
            atomicAdd(&g_cnt[clampi(d2.y)], 1);
        }
        return;
    }

    __nv_bfloat16* As = (__nv_bfloat16*)smbuf;            // [128][72]
    __nv_bfloat16* Bs = (__nv_bfloat16*)(smbuf + 18432);  // [128][72]
    unsigned short* Cs = (unsigned short*)smbuf;          // overlay
    int n0 = (blockIdx.x >> 1) * 128, c0 = (blockIdx.x & 1) * 128;
    int wm = wid >> 2, wn = wid & 3;
    uint32_t asb = (uint32_t)__cvta_generic_to_shared(As);
    uint32_t bsb = (uint32_t)__cvta_generic_to_shared(Bs);

    if (tid < 128) biasS[tid] = Wb[c0 + tid];

    float acc[4][4][4];
#pragma unroll
    for (int mt = 0; mt < 4; mt++)
#pragma unroll
        for (int nt = 0; nt < 4; nt++)
#pragma unroll
            for (int r = 0; r < 4; r++) acc[mt][nt][r] = 0.f;

    for (int kc = 0; kc < DXX; kc += 64) {
        __syncthreads();
#pragma unroll
        for (int j = 0; j < 8; j++) {
            int lin = tid + 256 * j;
            int row = lin >> 4, q = lin & 15;
            int gn = n0 + row; if (gn >= NN) gn = NN - 1;
            float4 v = *(const float4*)&x[(size_t)gn * DXX + kc + q * 4];
            uint2 o = make_uint2(pack_bf2(v.x, v.y), pack_bf2(v.z, v.w));
            *(uint2*)&As[row * 72 + q * 4] = o;
        }
#pragma unroll
        for (int j = 0; j < 8; j++) {
            int lin = tid + 256 * j;
            int row = lin >> 4, q = lin & 15;
            float4 v = *(const float4*)&Ww[(size_t)(c0 + row) * DXX + kc + q * 4];
            uint2 o = make_uint2(pack_bf2(v.x, v.y), pack_bf2(v.z, v.w));
            *(uint2*)&Bs[row * 72 + q * 4] = o;
        }
        __syncthreads();
#pragma unroll
        for (int ks = 0; ks < 4; ks++) {
            int k0 = ks * 16;
            uint32_t a[4][4], b[4][2];
#pragma unroll
            for (int mt = 0; mt < 4; mt++) {
                uint32_t ad = asb + ((wm * 64 + mt * 16 + (lane & 15)) * 72 +
                                     k0 + (lane >> 4) * 8) * 2;
                LDSM4(a[mt][0], a[mt][1], a[mt][2], a[mt][3], ad);
            }
#pragma unroll
            for (int nt = 0; nt < 4; nt++) {
                uint32_t bd = bsb + ((wn * 32 + nt * 8 + (lane & 7)) * 72 +
                                     k0 + ((lane >> 3) & 1) * 8) * 2;
                LDSM2(b[nt][0], b[nt][1], bd);
            }
#pragma unroll
            for (int mt = 0; mt < 4; mt++)
#pragma unroll
                for (int nt = 0; nt < 4; nt++)
                    MMA16816(acc[mt][nt], a[mt], b[nt]);
        }
    }
    __syncthreads();

    int tm = lane >> 2, tp = lane & 3;
#pragma unroll
    for (int mt = 0; mt < 4; mt++)
#pragma unroll
        for (int nt = 0; nt < 4; nt++) {
            int row = wm * 64 + mt * 16 + tm;
            int colp = wn * 16 + nt * 4 + tp;
            int c = colp * 2;
            unsigned short u0, u1;
            PACKF8(u0, acc[mt][nt][0] + biasS[c], acc[mt][nt][1] + biasS[c + 1]);
            PACKF8(u1, acc[mt][nt][2] + biasS[c], acc[mt][nt][3] + biasS[c + 1]);
            Cs[row * 72 + colp] = u0;
            Cs[(row + 8) * 72 + colp] = u1;
        }
    __syncthreads();
#pragma unroll
    for (int j = 0; j < 4; j++) {
        int lin = tid + 256 * j;
        int row = lin >> 3, q = lin & 7;
        int gn = n0 + row;
        if (gn < NN) {
            uint4 v = *(uint4*)&Cs[row * 72 + q * 8];
            ((uint4*)g_Wxf8)[(size_t)gn * 16 + (c0 >> 4) + q] = v;
        }
    }
}

// ---------------- K4abc: parallel exclusive scan (+1 self-loop folded) -----
__global__ __launch_bounds__(1024) void k_scan1() {
    __shared__ int wsum[32];
    int tid = threadIdx.x, lane = tid & 31, wid = tid >> 5;
    int i = blockIdx.x * 1024 + tid;
    int v = 0;
    if (i < NN) {
        v = g_cnt[i] + 1;        // +1 = self loop slot
        g_cnt[i] = 0;            // reset for next replay
    }
    int s = v;
#pragma unroll
    for (int o = 1; o < 32; o <<= 1) {
        int t = __shfl_up_sync(0xffffffffu, s, o);
        if (lane >= o) s += t;
    }
    if (lane == 31) wsum[wid] = s;
    __syncthreads();
    if (wid == 0) {
        int ws = wsum[lane];
#pragma unroll
        for (int o = 1; o < 32; o <<= 1) {
            int t = __shfl_up_sync(0xffffffffu, ws, o);
            if (lane >= o) ws += t;
        }
        wsum[lane] = ws;
    }
    __syncthreads();
    int incl = s + (wid > 0 ? wsum[wid - 1] : 0);
    if (i < NN) { g_rowptr[i + 1] = incl; g_cur[i] = incl - v; }
    if (tid == 1023) g_bsum[blockIdx.x] = incl;
}
__global__ void k_scan2() {       // 64 threads; also zeroes colsum
    int tid = threadIdx.x, lane = tid & 31, wid = tid >> 5;
    __shared__ int w0;
    for (int c = tid; c < CC; c += 64) g_colsum[c] = 0.f;
    int v = (tid < SCB) ? g_bsum[tid] : 0;
    int s = v;
#pragma unroll
    for (int o = 1; o < 32; o <<= 1) {
        int t = __shfl_up_sync(0xffffffffu, s, o);
        if (lane >= o) s += t;
    }
    if (tid == 31) w0 = s;
    __syncthreads();
    if (wid == 1) s += w0;
    if (tid < SCB) g_bsum[tid] = s - v;   // exclusive
}
__global__ __launch_bounds__(1024) void k_scan3() {
    int off = g_bsum[blockIdx.x];
    int i = blockIdx.x * 1024 + threadIdx.x;
    if (i < NN) { g_rowptr[i + 1] += off; g_cur[i] += off; }
    if (i == 0) g_rowptr[0] = 0;
}

// ---------------- F2: scatter ∥ scores --------------------------------------
__global__ __launch_bounds__(256) void k_f2(const float* __restrict__ aw,
                                            const float* __restrict__ ab,
                                            const int* __restrict__ ei) {
    int tid = threadIdx.x;
    if (blockIdx.x < F2_SCAT) {
        int i = blockIdx.x * 256 + tid;
        if (i < EE / 2) {
            int2 s2 = *(const int2*)&ei[2 * i];
            int2 d2 = *(const int2*)&ei[EE + 2 * i];
            int pa = atomicAdd(&g_cur[clampi(d2.x)], 1);
            int pb = atomicAdd(&g_cur[clampi(d2.y)], 1);
            if (pa < ETOT) g_csr[pa] = clampi(s2.x);
            if (pb < ETOT) g_csr[pb] = clampi(s2.y);
        } else {
            int n = i - EE / 2;
            if (n < NN) {
                int pos = atomicAdd(&g_cur[n], 1);
                if (pos < ETOT) g_csr[pos] = n;
            }
        }
        return;
    }
    int n = ((blockIdx.x - F2_SCAT) << 3) + (tid >> 5);
    int lane = tid & 31;
    if (n >= NN) return;
    int h = lane >> 3;
    int dd = (lane & 7) * 8;
    uint2 u = g_Wxf8[(size_t)n * 32 + lane];
    __half2 h0, h1, h2, h3;
    f8_to_f16x2(u.x, h0, h1);
    f8_to_f16x2(u.y, h2, h3);
    float2 p0 = __half22float2(h0), p1 = __half22float2(h1);
    float2 p2 = __half22float2(h2), p3 = __half22float2(h3);
    float f[8] = {p0.x, p0.y, p1.x, p1.y, p2.x, p2.y, p3.x, p3.y};
    const float* ai = aw + h * 128 + dd;
    const float* aj = ai + 64;
    float va = 0.f, vb = 0.f;
#pragma unroll
    for (int j = 0; j < 8; j++) { va += f[j] * ai[j]; vb += f[j] * aj[j]; }
#pragma unroll
    for (int o = 4; o; o >>= 1) {
        va += __shfl_xor_sync(0xffffffffu, va, o);
        vb += __shfl_xor_sync(0xffffffffu, vb, o);
    }
    if ((lane & 7) == 0) {
        g_sif[n * 4 + h] = (va + ab[h]) * LOG2E;
        g_sjf[n * 4 + h] = vb * LOG2E;
    }
}

// ---------------- K6: edge softmax; 2 warps per node, depth-4 pipe ---------
// Grid 12500 x 4 nodes/block (exactly NN). Warp pair splits the edge range;
// partials combine via smem. E = exp(acc/den) stored bf16.
__global__ __launch_bounds__(256) void k_agg() {
    __shared__ uint4 sacc[4][32];
    __shared__ float sden[4];
    int wid = threadIdx.x >> 5, lane = threadIdx.x & 31;
    int slot = wid >> 1, half = wid & 1;
    int n = (blockIdx.x << 2) + slot;          // always < NN (12500*4 == NN)
    int h = lane >> 3;
    int s = g_rowptr[n], en = g_rowptr[n + 1];
    int mid = s + ((en - s + 1) >> 1);         // warp0 gets the extra edge
    int ss = half ? mid : s;
    int ee = half ? en : mid;
    float si = g_sif[n * 4 + h];

    __half2 acc0 = __float2half2_rn(0.f), acc1 = acc0, acc2 = acc0, acc3 = acc0;
    float den = 0.f;

    if (ss < ee) {
        int srcA = g_csr[ss];
        int srcB = (ss + 1 < ee) ? g_csr[ss + 1] : srcA;
        float sjA = g_sjf[srcA * 4 + h], sjB = g_sjf[srcB * 4 + h];
        uint2 uA = g_Wxf8[(size_t)srcA * 32 + lane];
        uint2 uB = g_Wxf8[(size_t)srcB * 32 + lane];

        for (int e = ss; e < ee; e += 2) {
            int nA = (e + 2 < ee) ? g_csr[e + 2] : srcA;
            int nB = (e + 3 < ee) ? g_csr[e + 3] : srcA;
            float sjAn = g_sjf[nA * 4 + h];
            uint2 uAn = g_Wxf8[(size_t)nA * 32 + lane];
            float sjBn = g_sjf[nB * 4 + h];
            uint2 uBn = g_Wxf8[(size_t)nB * 32 + lane];

            {
                float t = si + sjA;
                t = fmaxf(t, NEG * t);
                float c; EX2A(c, t);
                den += c;
                __half2 ch = __float2half2_rn(c);
                __half2 w0, w1, w2, w3;
                f8_to_f16x2(uA.x, w0, w1);
                f8_to_f16x2(uA.y, w2, w3);
                acc0 = __hfma2(ch, w0, acc0);
                acc1 = __hfma2(ch, w1, acc1);
                acc2 = __hfma2(ch, w2, acc2);
                acc3 = __hfma2(ch, w3, acc3);
            }
            if (e + 1 < ee) {
                float t = si + sjB;
                t = fmaxf(t, NEG * t);
                float c; EX2A(c, t);
                den += c;
                __half2 ch = __float2half2_rn(c);
                __half2 w0, w1, w2, w3;
                f8_to_f16x2(uB.x, w0, w1);
                f8_to_f16x2(uB.y, w2, w3);
                acc0 = __hfma2(ch, w0, acc0);
                acc1 = __hfma2(ch, w1, acc1);
                acc2 = __hfma2(ch, w2, acc2);
                acc3 = __hfma2(ch, w3, acc3);
            }
            sjA = sjAn; uA = uAn; sjB = sjBn; uB = uBn;
        }
    }

    if (half) {
        if (lane == 0) sden[slot] = den;
        sacc[slot][lane] = make_uint4(*(unsigned*)&acc0, *(unsigned*)&acc1,
                                      *(unsigned*)&acc2, *(unsigned*)&acc3);
    }
    __syncthreads();
    if (!half) {
        uint4 o = sacc[slot][lane];
        acc0 = __hadd2(acc0, *(__half2*)&o.x);
        acc1 = __hadd2(acc1, *(__half2*)&o.y);
        acc2 = __hadd2(acc2, *(__half2*)&o.z);
        acc3 = __hadd2(acc3, *(__half2*)&o.w);
        den += sden[slot];
        float inv = 1.f / den;
        float2 f0 = __half22float2(acc0);
        float2 f1 = __half22float2(acc1);
        float2 f2 = __half22float2(acc2);
        float2 f3 = __half22float2(acc3);
        unsigned p0, p1, p2, p3;
        PACKBF(p0, __expf(f0.x * inv), __expf(f0.y * inv));
        PACKBF(p1, __expf(f1.x * inv), __expf(f1.y * inv));
        PACKBF(p2, __expf(f2.x * inv), __expf(f2.y * inv));
        PACKBF(p3, __expf(f3.x * inv), __expf(f3.y * inv));
        g_aggh4[(size_t)n * 32 + lane] = make_uint4(p0, p1, p2, p3);
    }
}

// ---------------- K7: column sum of E (1000 blocks x 50 rows) --------------
__global__ __launch_bounds__(256) void k_colsum() {
    const unsigned* Ah = (const unsigned*)g_aggh4;
    int tid = threadIdx.x;
    int c2 = tid & 127;                // uint index = column pair
    int g = tid >> 7;
    int n0 = blockIdx.x * 50;
    float s0 = 0.f, s1 = 0.f;
    for (int r = g; r < 50; r += 2) {
        unsigned u = Ah[(size_t)(n0 + r) * 128 + c2];
        s0 += bflo(u);
        s1 += bfhi(u);
    }
    atomicAdd(&g_colsum[c2 * 2], s0);
    atomicAdd(&g_colsum[c2 * 2 + 1], s1);
}

// ---------------- K8: out = (E*siv) @ Wo^T + b  (bf16 mma.sync) ------------
__global__ __launch_bounds__(256) void k_out(const float* __restrict__ Wo,
                                             const float* __restrict__ Wob,
                                             float* __restrict__ out) {
    __shared__ __align__(16) char smbuf[34816];
    __shared__ float sivS[CC];
    __nv_bfloat16* As = (__nv_bfloat16*)smbuf;            // [128][72]
    __nv_bfloat16* Bs = (__nv_bfloat16*)(smbuf + 18432);  // [64][72]
    float* Csf = (float*)smbuf;                           // overlay
    int tid = threadIdx.x, lane = tid & 31, wid = tid >> 5;
    int n0 = blockIdx.x * 128;
    int wm = wid & 3, wn = wid >> 2;
    uint32_t asb = (uint32_t)__cvta_generic_to_shared(As);
    uint32_t bsb = (uint32_t)__cvta_generic_to_shared(Bs);

    sivS[tid] = 1.f / g_colsum[tid];

    float acc[2][4][4];
#pragma unroll
    for (int mt = 0; mt < 2; mt++)
#pragma unroll
        for (int nt = 0; nt < 4; nt++)
#pragma unroll
            for (int r = 0; r < 4; r++) acc[mt][nt][r] = 0.f;

    for (int cb = 0; cb < CC; cb += 64) {
        __syncthreads();
#pragma unroll
        for (int j = 0; j < 4; j++) {
            int lin = tid + 256 * j;
            int row = lin >> 3, q = lin & 7;
            int gn = n0 + row; if (gn >= NN) gn = NN - 1;
            uint4 u = g_aggh4[(size_t)gn * 32 + (cb >> 3) + q];
            unsigned ua[4] = {u.x, u.y, u.z, u.w};
            unsigned ou[4];
#pragma unroll
            for (int i = 0; i < 4; i++) {
                int c = cb + q * 8 + 2 * i;
                ou[i] = pack_bf2(bflo(ua[i]) * sivS[c], bfhi(ua[i]) * sivS[c + 1]);
            }
            *(uint4*)&As[row * 72 + q * 8] = make_uint4(ou[0], ou[1], ou[2], ou[3]);
        }
#pragma unroll
        for (int j = 0; j < 4; j++) {
            int lin = tid + 256 * j;
            int row = lin >> 4, q = lin & 15;
            float4 v = *(const float4*)&Wo[(size_t)row * CC + cb + q * 4];
            uint2 o = make_uint2(pack_bf2(v.x, v.y), pack_bf2(v.z, v.w));
            *(uint2*)&Bs[row * 72 + q * 4] = o;
        }
        __syncthreads();
#pragma unroll
        for (int ks = 0; ks < 4; ks++) {
            int k0 = ks * 16;
            uint32_t a[2][4], b[4][2];
#pragma unroll
            for (int mt = 0; mt < 2; mt++) {
                uint32_t ad = asb + ((wm * 32 + mt * 16 + (lane & 15)) * 72 +
                                     k0 + (lane >> 4) * 8) * 2;
                LDSM4(a[mt][0], a[mt][1], a[mt][2], a[mt][3], ad);
            }
#pragma unroll
            for (int nt = 0; nt < 4; nt++) {
                uint32_t bd = bsb + ((wn * 32 + nt * 8 + (lane & 7)) * 72 +
                                     k0 + ((lane >> 3) & 1) * 8) * 2;
                LDSM2(b[nt][0], b[nt][1], bd);
            }
#pragma unroll
            for (int mt = 0; mt < 2; mt++)
#pragma unroll
                for (int nt = 0; nt < 4; nt++)
                    MMA16816(acc[mt][nt], a[mt], b[nt]);
        }
    }
    __syncthreads();

    int tm = lane >> 2, tp = lane & 3;
#pragma unroll
    for (int mt = 0; mt < 2; mt++)
#pragma unroll
        for (int nt = 0; nt < 4; nt++) {
            int row = wm * 32 + mt * 16 + tm;
            int col = wn * 32 + nt * 8 + 2 * tp;
            Csf[row * 68 + col] = acc[mt][nt][0];
            Csf[row * 68 + col + 1] = acc[mt][nt][1];
            Csf[(row + 8) * 68 + col] = acc[mt][nt][2];
            Csf[(row + 8) * 68 + col + 1] = acc[mt][nt][3];
        }
    __syncthreads();
#pragma unroll
    for (int j = 0; j < 8; j++) {
        int lin = tid + 256 * j;
        int row = lin >> 4, q = lin & 15;
        int gn = n0 + row;
        if (gn < NN) {
            float4 v = *(float4*)&Csf[row * 68 + q * 4];
            float4 b = *(const float4*)&Wob[q * 4];
            float4 o = {v.x + b.x, v.y + b.y, v.z + b.z, v.w + b.w};
            *(float4*)&out[(size_t)gn * 64 + q * 4] = o;
        }
    }
}

// ---------------- launch ----------------------------------------------------
extern "C" void kernel_launch(void* const* d_in, const int* in_sizes, int n_in,
                              void* d_out, int out_size) {
    (void)out_size;
    const void* p[8];
    for (int j = 0; j < 8; j++) p[j] = (j < n_in) ? d_in[j] : 0;
    const int want[8] = {2 * EE, NN * DXX, KH * DHH * DXX, KH * DHH,
                         KH * 2 * DHH, KH, DHH * CC, DHH};
    for (int j = 0; j < 8; j++)
        for (int i = 0; i < n_in; i++)
            if (in_sizes[i] == want[j]) { p[j] = d_in[i]; break; }

    const int*   ei  = (const int*)p[0];
    const float* x   = (const float*)p[1];
    const float* Ww  = (const float*)p[2];
    const float* Wb  = (const float*)p[3];
    const float* aw  = (const float*)p[4];
    const float* ab  = (const float*)p[5];
    const float* Wo  = (const float*)p[6];
    const float* Wob = (const float*)p[7];
    float* out = (float*)d_out;

    k_f1<<<F1_WX + F1_HIST, 256>>>(x, Ww, Wb, ei);
    k_scan1<<<SCB, 1024>>>();
    k_scan2<<<1, 64>>>();
    k_scan3<<<SCB, 1024>>>();
    k_f2<<<F2_SCAT + F2_SCORE, 256>>>(aw, ab, ei);
    k_agg<<<NN / 4, 256>>>();
    k_colsum<<<1000, 256>>>();
    k_out<<<391, 256>>>(Wo, Wob, out);
}

// round 12
// speedup vs baseline: 1.0545x; 1.0545x over previous
#include <cuda_runtime.h>
#include <cuda_bf16.h>
#include <cuda_fp16.h>
#include <cstdint>

typedef unsigned long long ull;

#define NN 50000
#define EE 1600000
#define ETOT 1650000
#define KH 4
#define DHH 64
#define DXX 128
#define CC 256          // KH*DHH
#define NEG 0.01f
#define SCB 49          // scan blocks (49*1024 >= NN)
#define LOG2E 1.44269504f

// f1: blocks [0,782) = wx tiles, then hist (4 edges/thread)
#define F1_WX 782
#define F1_HIST 1563
// f2: scatter (4 edges/thread + self loops), then scores
#define F2_SCAT 1758
#define F2_SCORE 6250

// ---------------- scratch (static device globals; zero-init at load) --------
__device__ uint2 g_Wxf8[NN * 32];        // 12.8 MB  fp8 Wx[n][c] (256B/row)
__device__ uint4 g_aggh4[NN * 32];       // 25.6 MB  bf16 E = exp(agg)
__device__ float g_sif[NN * KH];         // (si + ab) * log2e, per head
__device__ float g_sjf[NN * KH];         // sj * log2e, per head
__device__ int g_cnt[NN];                // zero-init; re-zeroed by scan1
__device__ int g_rowptr[NN + 1];
__device__ int g_cur[NN];
__device__ int g_bsum[64];
__device__ int g_csr[ETOT];              // src indices grouped by dst
__device__ float g_colsum[CC];           // re-zeroed by scan2

// ---------------- helpers ---------------------------------------------------
__device__ __forceinline__ float bflo(unsigned u) { return __uint_as_float(u << 16); }
__device__ __forceinline__ float bfhi(unsigned u) { return __uint_as_float(u & 0xffff0000u); }
__device__ __forceinline__ int clampi(int v) {
    return v < 0 ? 0 : (v >= NN ? NN - 1 : v);
}

#define PACKBF(r, lo, hi) asm("cvt.rn.bf16x2.f32 %0, %1, %2;" : "=r"(r) : "f"(hi), "f"(lo))
#define PACKF8(r, lo, hi) \
    asm("cvt.rn.satfinite.e4m3x2.f32 %0, %1, %2;" : "=h"(r) : "f"(hi), "f"(lo))
#define UNPF8(d, s) asm("cvt.rn.f16x2.e4m3x2 %0, %1;" : "=r"(d) : "h"(s))
#define EX2A(d, s) asm("ex2.approx.ftz.f32 %0, %1;" : "=f"(d) : "f"(s))

__device__ __forceinline__ void f8_to_f16x2(unsigned u32v, __half2& lo, __half2& hi) {
    unsigned short sl = (unsigned short)(u32v & 0xffffu);
    unsigned short sh = (unsigned short)(u32v >> 16);
    unsigned a, b;
    UNPF8(a, sl);
    UNPF8(b, sh);
    lo = *(__half2*)&a;
    hi = *(__half2*)&b;
}

#define LDSM4(r0, r1, r2, r3, a) asm volatile( \
    "ldmatrix.sync.aligned.m8n8.x4.shared.b16 {%0,%1,%2,%3}, [%4];" \
    : "=r"(r0), "=r"(r1), "=r"(r2), "=r"(r3) : "r"(a))
#define LDSM2(r0, r1, a) asm volatile( \
    "ldmatrix.sync.aligned.m8n8.x2.shared.b16 {%0,%1}, [%2];" \
    : "=r"(r0), "=r"(r1) : "r"(a))
#define MMA16816(d, a, b) asm volatile( \
    "mma.sync.aligned.m16n8k16.row.col.f32.bf16.bf16.f32 " \
    "{%0,%1,%2,%3}, {%4,%5,%6,%7}, {%8,%9}, {%0,%1,%2,%3};" \
    : "+f"((d)[0]), "+f"((d)[1]), "+f"((d)[2]), "+f"((d)[3]) \
    : "r"((a)[0]), "r"((a)[1]), "r"((a)[2]), "r"((a)[3]), "r"((b)[0]), "r"((b)[1]))

__device__ __forceinline__ unsigned pack_bf2(float lo, float hi) {
    unsigned r; PACKBF(r, lo, hi); return r;
}

// ---------------- F1: Wx GEMM (bf16 mma.sync, fp8 out) ∥ degree hist -------
__global__ __launch_bounds__(256) void k_f1(const float* __restrict__ x,
                                            const float* __restrict__ Ww,
                                            const float* __restrict__ Wb,
                                            const int* __restrict__ ei) {
    __shared__ __align__(16) char smbuf[36864];
    __shared__ float biasS[128];
    int tid = threadIdx.x, lane = tid & 31, wid = tid >> 5;

    if (blockIdx.x >= F1_WX) {
        // ---- hist role: 4 edges/thread ----
        int i = (blockIdx.x - F1_WX) * 256 + tid;
        if (i < EE / 4) {
            int4 d4 = *(const int4*)&ei[EE + 4 * i];
            atomicAdd(&g_cnt[clampi(d4.x)], 1);
            atomicAdd(&g_cnt[clampi(d4.y)], 1);
            atomicAdd(&g_cnt[clampi(d4.z)], 1);
            atomicAdd(&g_cnt[clampi(d4.w)], 1);
        }
        return;
    }

    __nv_bfloat16* As = (__nv_bfloat16*)smbuf;            // [128][72]
    __nv_bfloat16* Bs = (__nv_bfloat16*)(smbuf + 18432);  // [128][72]
    unsigned short* Cs = (unsigned short*)smbuf;          // overlay
    int n0 = (blockIdx.x >> 1) * 128, c0 = (blockIdx.x & 1) * 128;
    int wm = wid >> 2, wn = wid & 3;
    uint32_t asb = (uint32_t)__cvta_generic_to_shared(As);
    uint32_t bsb = (uint32_t)__cvta_generic_to_shared(Bs);

    if (tid < 128) biasS[tid] = Wb[c0 + tid];

    float acc[4][4][4];
#pragma unroll
    for (int mt = 0; mt < 4; mt++)
#pragma unroll
        for (int nt = 0; nt < 4; nt++)
#pragma unroll
            for (int r = 0; r < 4; r++) acc[mt][nt][r] = 0.f;

    for (int kc = 0; kc < DXX; kc += 64) {
        __syncthreads();
#pragma unroll
        for (int j = 0; j < 8; j++) {
            int lin = tid + 256 * j;
            int row = lin >> 4, q = lin & 15;
            int gn = n0 + row; if (gn >= NN) gn = NN - 1;
            float4 v = *(const float4*)&x[(size_t)gn * DXX + kc + q * 4];
            uint2 o = make_uint2(pack_bf2(v.x, v.y), pack_bf2(v.z, v.w));
            *(uint2*)&As[row * 72 + q * 4] = o;
        }
#pragma unroll
        for (int j = 0; j < 8; j++) {
            int lin = tid + 256 * j;
            int row = lin >> 4, q = lin & 15;
            float4 v = *(const float4*)&Ww[(size_t)(c0 + row) * DXX + kc + q * 4];
            uint2 o = make_uint2(pack_bf2(v.x, v.y), pack_bf2(v.z, v.w));
            *(uint2*)&Bs[row * 72 + q * 4] = o;
        }
        __syncthreads();
#pragma unroll
        for (int ks = 0; ks < 4; ks++) {
            int k0 = ks * 16;
            uint32_t a[4][4], b[4][2];
#pragma unroll
            for (int mt = 0; mt < 4; mt++) {
                uint32_t ad = asb + ((wm * 64 + mt * 16 + (lane & 15)) * 72 +
                                     k0 + (lane >> 4) * 8) * 2;
                LDSM4(a[mt][0], a[mt][1], a[mt][2], a[mt][3], ad);
            }
#pragma unroll
            for (int nt = 0; nt < 4; nt++) {
                uint32_t bd = bsb + ((wn * 32 + nt * 8 + (lane & 7)) * 72 +
                                     k0 + ((lane >> 3) & 1) * 8) * 2;
                LDSM2(b[nt][0], b[nt][1], bd);
            }
#pragma unroll
            for (int mt = 0; mt < 4; mt++)
#pragma unroll
                for (int nt = 0; nt < 4; nt++)
                    MMA16816(acc[mt][nt], a[mt], b[nt]);
        }
    }
    __syncthreads();

    int tm = lane >> 2, tp = lane & 3;
#pragma unroll
    for (int mt = 0; mt < 4; mt++)
#pragma unroll
        for (int nt = 0; nt < 4; nt++) {
            int row = wm * 64 + mt * 16 + tm;
            int colp = wn * 16 + nt * 4 + tp;
            int c = colp * 2;
            unsigned short u0, u1;
            PACKF8(u0, acc[mt][nt][0] + biasS[c], acc[mt][nt][1] + biasS[c + 1]);
            PACKF8(u1, acc[mt][nt][2] + biasS[c], acc[mt][nt][3] + biasS[c + 1]);
            Cs[row * 72 + colp] = u0;
            Cs[(row + 8) * 72 + colp] = u1;
        }
    __syncthreads();
#pragma unroll
    for (int j = 0; j < 4; j++) {
        int lin = tid + 256 * j;
        int row = lin >> 3, q = lin & 7;
        int gn = n0 + row;
        if (gn < NN) {
            uint4 v = *(uint4*)&Cs[row * 72 + q * 8];
            ((uint4*)g_Wxf8)[(size_t)gn * 16 + (c0 >> 4) + q] = v;
        }
    }
}

// ---------------- K4abc: parallel exclusive scan (+1 self-loop folded) -----
__global__ __launch_bounds__(1024) void k_scan1() {
    __shared__ int wsum[32];
    int tid = threadIdx.x, lane = tid & 31, wid = tid >> 5;
    int i = blockIdx.x * 1024 + tid;
    int v = 0;
    if (i < NN) {
        v = g_cnt[i] + 1;        // +1 = self loop slot
        g_cnt[i] = 0;            // reset for next replay
    }
    int s = v;
#pragma unroll
    for (int o = 1; o < 32; o <<= 1) {
        int t = __shfl_up_sync(0xffffffffu, s, o);
        if (lane >= o) s += t;
    }
    if (lane == 31) wsum[wid] = s;
    __syncthreads();
    if (wid == 0) {
        int ws = wsum[lane];
#pragma unroll
        for (int o = 1; o < 32; o <<= 1) {
            int t = __shfl_up_sync(0xffffffffu, ws, o);
            if (lane >= o) ws += t;
        }
        wsum[lane] = ws;
    }
    __syncthreads();
    int incl = s + (wid > 0 ? wsum[wid - 1] : 0);
    if (i < NN) { g_rowptr[i + 1] = incl; g_cur[i] = incl - v; }
    if (tid == 1023) g_bsum[blockIdx.x] = incl;
}
__global__ void k_scan2() {       // 64 threads; also zeroes colsum
    int tid = threadIdx.x, lane = tid & 31, wid = tid >> 5;
    __shared__ int w0;
    for (int c = tid; c < CC; c += 64) g_colsum[c] = 0.f;
    int v = (tid < SCB) ? g_bsum[tid] : 0;
    int s = v;
#pragma unroll
    for (int o = 1; o < 32; o <<= 1) {
        int t = __shfl_up_sync(0xffffffffu, s, o);
        if (lane >= o) s += t;
    }
    if (tid == 31) w0 = s;
    __syncthreads();
    if (wid == 1) s += w0;
    if (tid < SCB) g_bsum[tid] = s - v;   // exclusive
}
__global__ __launch_bounds__(1024) void k_scan3() {
    int off = g_bsum[blockIdx.x];
    int i = blockIdx.x * 1024 + threadIdx.x;
    if (i < NN) { g_rowptr[i + 1] += off; g_cur[i] += off; }
    if (i == 0) g_rowptr[0] = 0;
}

// ---------------- F2: scatter (4 edges/thread) ∥ scores ---------------------
__global__ __launch_bounds__(256) void k_f2(const float* __restrict__ aw,
                                            const float* __restrict__ ab,
                                            const int* __restrict__ ei) {
    int tid = threadIdx.x;
    if (blockIdx.x < F2_SCAT) {
        int i = blockIdx.x * 256 + tid;
        if (i < EE / 4) {
            int4 s4 = *(const int4*)&ei[4 * i];
            int4 d4 = *(const int4*)&ei[EE + 4 * i];
            int pa = atomicAdd(&g_cur[clampi(d4.x)], 1);
            int pb = atomicAdd(&g_cur[clampi(d4.y)], 1);
            int pc = atomicAdd(&g_cur[clampi(d4.z)], 1);
            int pd = atomicAdd(&g_cur[clampi(d4.w)], 1);
            if (pa < ETOT) g_csr[pa] = clampi(s4.x);
            if (pb < ETOT) g_csr[pb] = clampi(s4.y);
            if (pc < ETOT) g_csr[pc] = clampi(s4.z);
            if (pd < ETOT) g_csr[pd] = clampi(s4.w);
        } else {
            int n = i - EE / 4;
            if (n < NN) {
                int pos = atomicAdd(&g_cur[n], 1);
                if (pos < ETOT) g_csr[pos] = n;
            }
        }
        return;
    }
    int n = ((blockIdx.x - F2_SCAT) << 3) + (tid >> 5);
    int lane = tid & 31;
    if (n >= NN) return;
    int h = lane >> 3;
    int dd = (lane & 7) * 8;
    uint2 u = g_Wxf8[(size_t)n * 32 + lane];
    __half2 h0, h1, h2, h3;
    f8_to_f16x2(u.x, h0, h1);
    f8_to_f16x2(u.y, h2, h3);
    float2 p0 = __half22float2(h0), p1 = __half22float2(h1);
    float2 p2 = __half22float2(h2), p3 = __half22float2(h3);
    float f[8] = {p0.x, p0.y, p1.x, p1.y, p2.x, p2.y, p3.x, p3.y};
    const float* ai = aw + h * 128 + dd;
    const float* aj = ai + 64;
    float va = 0.f, vb = 0.f;
#pragma unroll
    for (int j = 0; j < 8; j++) { va += f[j] * ai[j]; vb += f[j] * aj[j]; }
#pragma unroll
    for (int o = 4; o; o >>= 1) {
        va += __shfl_xor_sync(0xffffffffu, va, o);
        vb += __shfl_xor_sync(0xffffffffu, vb, o);
    }
    if ((lane & 7) == 0) {
        g_sif[n * 4 + h] = (va + ab[h]) * LOG2E;
        g_sjf[n * 4 + h] = vb * LOG2E;
    }
}

// ---------------- K6: edge softmax + fp8 gather, depth-4 pipe (R9) ---------
__global__ __launch_bounds__(256) void k_agg() {
    int n = (blockIdx.x << 3) + (threadIdx.x >> 5);
    int lane = threadIdx.x & 31;
    if (n >= NN) return;
    int h = lane >> 3;
    int s = g_rowptr[n], en = g_rowptr[n + 1];
    float si = g_sif[n * 4 + h];

    __half2 acc0 = __float2half2_rn(0.f), acc1 = acc0, acc2 = acc0, acc3 = acc0;
    float den = 0.f;

    int srcA = g_csr[s];
    int srcB = (s + 1 < en) ? g_csr[s + 1] : srcA;
    float sjA = g_sjf[srcA * 4 + h], sjB = g_sjf[srcB * 4 + h];
    uint2 uA = g_Wxf8[(size_t)srcA * 32 + lane];
    uint2 uB = g_Wxf8[(size_t)srcB * 32 + lane];

    for (int e = s; e < en; e += 2) {
        int nA = (e + 2 < en) ? g_csr[e + 2] : srcA;
        int nB = (e + 3 < en) ? g_csr[e + 3] : srcA;
        float sjAn = g_sjf[nA * 4 + h];
        uint2 uAn = g_Wxf8[(size_t)nA * 32 + lane];
        float sjBn = g_sjf[nB * 4 + h];
        uint2 uBn = g_Wxf8[(size_t)nB * 32 + lane];

        {
            float t = si + sjA;
            t = fmaxf(t, NEG * t);
            float c; EX2A(c, t);
            den += c;
            __half2 ch = __float2half2_rn(c);
            __half2 w0, w1, w2, w3;
            f8_to_f16x2(uA.x, w0, w1);
            f8_to_f16x2(uA.y, w2, w3);
            acc0 = __hfma2(ch, w0, acc0);
            acc1 = __hfma2(ch, w1, acc1);
            acc2 = __hfma2(ch, w2, acc2);
            acc3 = __hfma2(ch, w3, acc3);
        }
        if (e + 1 < en) {
            float t = si + sjB;
            t = fmaxf(t, NEG * t);
            float c; EX2A(c, t);
            den += c;
            __half2 ch = __float2half2_rn(c);
            __half2 w0, w1, w2, w3;
            f8_to_f16x2(uB.x, w0, w1);
            f8_to_f16x2(uB.y, w2, w3);
            acc0 = __hfma2(ch, w0, acc0);
            acc1 = __hfma2(ch, w1, acc1);
            acc2 = __hfma2(ch, w2, acc2);
            acc3 = __hfma2(ch, w3, acc3);
        }
        sjA = sjAn; uA = uAn; sjB = sjBn; uB = uBn;
    }
    float inv = 1.f / den;
    float2 f0 = __half22float2(acc0);
    float2 f1 = __half22float2(acc1);
    float2 f2 = __half22float2(acc2);
    float2 f3 = __half22float2(acc3);
    unsigned p0, p1, p2, p3;
    PACKBF(p0, __expf(f0.x * inv), __expf(f0.y * inv));
    PACKBF(p1, __expf(f1.x * inv), __expf(f1.y * inv));
    PACKBF(p2, __expf(f2.x * inv), __expf(f2.y * inv));
    PACKBF(p3, __expf(f3.x * inv), __expf(f3.y * inv));
    g_aggh4[(size_t)n * 32 + lane] = make_uint4(p0, p1, p2, p3);
}

// ---------------- K7: column sum of E (1000 blocks x 50 rows) --------------
__global__ __launch_bounds__(256) void k_colsum() {
    const unsigned* Ah = (const unsigned*)g_aggh4;
    int tid = threadIdx.x;
    int c2 = tid & 127;                // uint index = column pair
    int g = tid >> 7;
    int n0 = blockIdx.x * 50;
    float s0 = 0.f, s1 = 0.f;
    for (int r = g; r < 50; r += 2) {
        unsigned u = Ah[(size_t)(n0 + r) * 128 + c2];
        s0 += bflo(u);
        s1 += bfhi(u);
    }
    atomicAdd(&g_colsum[c2 * 2], s0);
    atomicAdd(&g_colsum[c2 * 2 + 1], s1);
}

// ---------------- K8: out = (E*siv) @ Wo^T + b  (bf16 mma.sync) ------------
__global__ __launch_bounds__(256) void k_out(const float* __restrict__ Wo,
                                             const float* __restrict__ Wob,
                                             float* __restrict__ out) {
    __shared__ __align__(16) char smbuf[34816];
    __shared__ float sivS[CC];
    __nv_bfloat16* As = (__nv_bfloat16*)smbuf;            // [128][72]
    __nv_bfloat16* Bs = (__nv_bfloat16*)(smbuf + 18432);  // [64][72]
    float* Csf = (float*)smbuf;                           // overlay
    int tid = threadIdx.x, lane = tid & 31, wid = tid >> 5;
    int n0 = blockIdx.x * 128;
    int wm = wid & 3, wn = wid >> 2;
    uint32_t asb = (uint32_t)__cvta_generic_to_shared(As);
    uint32_t bsb = (uint32_t)__cvta_generic_to_shared(Bs);

    sivS[tid] = 1.f / g_colsum[tid];

    float acc[2][4][4];
#pragma unroll
    for (int mt = 0; mt < 2; mt++)
#pragma unroll
        for (int nt = 0; nt < 4; nt++)
#pragma unroll
            for (int r = 0; r < 4; r++) acc[mt][nt][r] = 0.f;

    for (int cb = 0; cb < CC; cb += 64) {
        __syncthreads();
#pragma unroll
        for (int j = 0; j < 4; j++) {
            int lin = tid + 256 * j;
            int row = lin >> 3, q = lin & 7;
            int gn = n0 + row; if (gn >= NN) gn = NN - 1;
            uint4 u = g_aggh4[(size_t)gn * 32 + (cb >> 3) + q];
            unsigned ua[4] = {u.x, u.y, u.z, u.w};
            unsigned ou[4];
#pragma unroll
            for (int i = 0; i < 4; i++) {
                int c = cb + q * 8 + 2 * i;
                ou[i] = pack_bf2(bflo(ua[i]) * sivS[c], bfhi(ua[i]) * sivS[c + 1]);
            }
            *(uint4*)&As[row * 72 + q * 8] = make_uint4(ou[0], ou[1], ou[2], ou[3]);
        }
#pragma unroll
        for (int j = 0; j < 4; j++) {
            int lin = tid + 256 * j;
            int row = lin >> 4, q = lin & 15;
            float4 v = *(const float4*)&Wo[(size_t)row * CC + cb + q * 4];
            uint2 o = make_uint2(pack_bf2(v.x, v.y), pack_bf2(v.z, v.w));
            *(uint2*)&Bs[row * 72 + q * 4] = o;
        }
        __syncthreads();
#pragma unroll
        for (int ks = 0; ks < 4; ks++) {
            int k0 = ks * 16;
            uint32_t a[2][4], b[4][2];
#pragma unroll
            for (int mt = 0; mt < 2; mt++) {
                uint32_t ad = asb + ((wm * 32 + mt * 16 + (lane & 15)) * 72 +
                                     k0 + (lane >> 4) * 8) * 2;
                LDSM4(a[mt][0], a[mt][1], a[mt][2], a[mt][3], ad);
            }
#pragma unroll
            for (int nt = 0; nt < 4; nt++) {
                uint32_t bd = bsb + ((wn * 32 + nt * 8 + (lane & 7)) * 72 +
                                     k0 + ((lane >> 3) & 1) * 8) * 2;
                LDSM2(b[nt][0], b[nt][1], bd);
            }
#pragma unroll
            for (int mt = 0; mt < 2; mt++)
#pragma unroll
                for (int nt = 0; nt < 4; nt++)
                    MMA16816(acc[mt][nt], a[mt], b[nt]);
        }
    }
    __syncthreads();

    int tm = lane >> 2, tp = lane & 3;
#pragma unroll
    for (int mt = 0; mt < 2; mt++)
#pragma unroll
        for (int nt = 0; nt < 4; nt++) {
            int row = wm * 32 + mt * 16 + tm;
            int col = wn * 32 + nt * 8 + 2 * tp;
            Csf[row * 68 + col] = acc[mt][nt][0];
            Csf[row * 68 + col + 1] = acc[mt][nt][1];
            Csf[(row + 8) * 68 + col] = acc[mt][nt][2];
            Csf[(row + 8) * 68 + col + 1] = acc[mt][nt][3];
        }
    __syncthreads();
#pragma unroll
    for (int j = 0; j < 8; j++) {
        int lin = tid + 256 * j;
        int row = lin >> 4, q = lin & 15;
        int gn = n0 + row;
        if (gn < NN) {
            float4 v = *(float4*)&Csf[row * 68 + q * 4];
            float4 b = *(const float4*)&Wob[q * 4];
            float4 o = {v.x + b.x, v.y + b.y, v.z + b.z, v.w + b.w};
            *(float4*)&out[(size_t)gn * 64 + q * 4] = o;
        }
    }
}

// ---------------- launch ----------------------------------------------------
extern "C" void kernel_launch(void* const* d_in, const int* in_sizes, int n_in,
                              void* d_out, int out_size) {
    (void)out_size;
    const void* p[8];
    for (int j = 0; j < 8; j++) p[j] = (j < n_in) ? d_in[j] : 0;
    const int want[8] = {2 * EE, NN * DXX, KH * DHH * DXX, KH * DHH,
                         KH * 2 * DHH, KH, DHH * CC, DHH};
    for (int j = 0; j < 8; j++)
        for (int i = 0; i < n_in; i++)
            if (in_sizes[i] == want[j]) { p[j] = d_in[i]; break; }

    const int*   ei  = (const int*)p[0];
    const float* x   = (const float*)p[1];
    const float* Ww  = (const float*)p[2];
    const float* Wb  = (const float*)p[3];
    const float* aw  = (const float*)p[4];
    const float* ab  = (const float*)p[5];
    const float* Wo  = (const float*)p[6];
    const float* Wob = (const float*)p[7];
    float* out = (float*)d_out;

    k_f1<<<F1_WX + F1_HIST, 256>>>(x, Ww, Wb, ei);
    k_scan1<<<SCB, 1024>>>();
    k_scan2<<<1, 64>>>();
    k_scan3<<<SCB, 1024>>>();
    k_f2<<<F2_SCAT + F2_SCORE, 256>>>(aw, ab, ei);
    k_agg<<<(NN + 7) / 8, 256>>>();
    k_colsum<<<1000, 256>>>();
    k_out<<<391, 256>>>(Wo, Wob, out);
}

// round 13
// speedup vs baseline: 1.1611x; 1.1010x over previous
#include <cuda_runtime.h>
#include <cuda_bf16.h>
#include <cuda_fp16.h>
#include <cstdint>

typedef unsigned long long ull;

#define NN 50000
#define EE 1600000
#define ETOT 1650000
#define KH 4
#define DHH 64
#define DXX 128
#define CC 256          // KH*DHH
#define NEG 0.01f
#define SCB 49          // scan blocks (49*1024 >= NN)
#define LOG2E 1.44269504f

// f1: blocks [0,782) = wx tiles, then hist (2 edges/thread)
#define F1_WX 782
#define F1_HIST 3125
// f2: scatter (2 edges/thread + self loops), then scores
#define F2_SCAT 3321
#define F2_SCORE 6250

// ---------------- scratch (static device globals; zero-init at load) --------
__device__ uint2 g_Wxf8[NN * 32];        // 12.8 MB  fp8 Wx[n][c] (256B/row)
__device__ uint4 g_aggh4[NN * 32];       // 25.6 MB  bf16 E = exp(agg)
__device__ float g_sif[NN * KH];         // (si + ab) * log2e, per head
__device__ float g_sjf[NN * KH];         // sj * log2e, per head
__device__ int g_cnt[NN];                // zero-init; re-zeroed by scan1
__device__ int g_rowptr[NN + 1];
__device__ int g_cur[NN];
__device__ int g_bsum[64];
__device__ int g_csr[ETOT];              // src indices grouped by dst
__device__ float g_colsum[CC];           // re-zeroed by scan2

// ---------------- helpers ---------------------------------------------------
__device__ __forceinline__ float bflo(unsigned u) { return __uint_as_float(u << 16); }
__device__ __forceinline__ float bfhi(unsigned u) { return __uint_as_float(u & 0xffff0000u); }
__device__ __forceinline__ int clampi(int v) {
    return v < 0 ? 0 : (v >= NN ? NN - 1 : v);
}

#define PACKBF(r, lo, hi) asm("cvt.rn.bf16x2.f32 %0, %1, %2;" : "=r"(r) : "f"(hi), "f"(lo))
#define PACKF8(r, lo, hi) \
    asm("cvt.rn.satfinite.e4m3x2.f32 %0, %1, %2;" : "=h"(r) : "f"(hi), "f"(lo))
#define UNPF8(d, s) asm("cvt.rn.f16x2.e4m3x2 %0, %1;" : "=r"(d) : "h"(s))
#define EX2A(d, s) asm("ex2.approx.ftz.f32 %0, %1;" : "=f"(d) : "f"(s))

__device__ __forceinline__ void f8_to_f16x2(unsigned u32v, __half2& lo, __half2& hi) {
    unsigned short sl = (unsigned short)(u32v & 0xffffu);
    unsigned short sh = (unsigned short)(u32v >> 16);
    unsigned a, b;
    UNPF8(a, sl);
    UNPF8(b, sh);
    lo = *(__half2*)&a;
    hi = *(__half2*)&b;
}

#define LDSM4(r0, r1, r2, r3, a) asm volatile( \
    "ldmatrix.sync.aligned.m8n8.x4.shared.b16 {%0,%1,%2,%3}, [%4];" \
    : "=r"(r0), "=r"(r1), "=r"(r2), "=r"(r3) : "r"(a))
#define LDSM2(r0, r1, a) asm volatile( \
    "ldmatrix.sync.aligned.m8n8.x2.shared.b16 {%0,%1}, [%2];" \
    : "=r"(r0), "=r"(r1) : "r"(a))
#define MMA16816(d, a, b) asm volatile( \
    "mma.sync.aligned.m16n8k16.row.col.f32.bf16.bf16.f32 " \
    "{%0,%1,%2,%3}, {%4,%5,%6,%7}, {%8,%9}, {%0,%1,%2,%3};" \
    : "+f"((d)[0]), "+f"((d)[1]), "+f"((d)[2]), "+f"((d)[3]) \
    : "r"((a)[0]), "r"((a)[1]), "r"((a)[2]), "r"((a)[3]), "r"((b)[0]), "r"((b)[1]))

__device__ __forceinline__ unsigned pack_bf2(float lo, float hi) {
    unsigned r; PACKBF(r, lo, hi); return r;
}

// ---------------- F1: Wx GEMM (bf16 mma.sync, fp8 out) ∥ degree hist -------
__global__ __launch_bounds__(256) void k_f1(const float* __restrict__ x,
                                            const float* __restrict__ Ww,
                                            const float* __restrict__ Wb,
                                            const int* __restrict__ ei) {
    __shared__ __align__(16) char smbuf[36864];
    __shared__ float biasS[128];
    int tid = threadIdx.x, lane = tid & 31, wid = tid >> 5;

    if (blockIdx.x >= F1_WX) {
        // ---- hist role: 2 edges/thread ----
        int i = (blockIdx.x - F1_WX) * 256 + tid;
        if (i < EE / 2) {
            int2 d2 = *(const int2*)&ei[EE + 2 * i];
            atomicAdd(&g_cnt[clampi(d2.x)], 1);
            atomicAdd(&g_cnt[clampi(d2.y)], 1);
        }
        return;
    }

    __nv_bfloat16* As = (__nv_bfloat16*)smbuf;            // [128][72]
    __nv_bfloat16* Bs = (__nv_bfloat16*)(smbuf + 18432);  // [128][72]
    unsigned short* Cs = (unsigned short*)smbuf;          // overlay
    int n0 = (blockIdx.x >> 1) * 128, c0 = (blockIdx.x & 1) * 128;
    int wm = wid >> 2, wn = wid & 3;
    uint32_t asb = (uint32_t)__cvta_generic_to_shared(As);
    uint32_t bsb = (uint32_t)__cvta_generic_to_shared(Bs);

    if (tid < 128) biasS[tid] = Wb[c0 + tid];

    float acc[4][4][4];
#pragma unroll
    for (int mt = 0; mt < 4; mt++)
#pragma unroll
        for (int nt = 0; nt < 4; nt++)
#pragma unroll
            for (int r = 0; r < 4; r++) acc[mt][nt][r] = 0.f;

    for (int kc = 0; kc < DXX; kc += 64) {
        __syncthreads();
#pragma unroll
        for (int j = 0; j < 8; j++) {
            int lin = tid + 256 * j;
            int row = lin >> 4, q = lin & 15;
            int gn = n0 + row; if (gn >= NN) gn = NN - 1;
            float4 v = *(const float4*)&x[(size_t)gn * DXX + kc + q * 4];
            uint2 o = make_uint2(pack_bf2(v.x, v.y), pack_bf2(v.z, v.w));
            *(uint2*)&As[row * 72 + q * 4] = o;
        }
#pragma unroll
        for (int j = 0; j < 8; j++) {
            int lin = tid + 256 * j;
            int row = lin >> 4, q = lin & 15;
            float4 v = *(const float4*)&Ww[(size_t)(c0 + row) * DXX + kc + q * 4];
            uint2 o = make_uint2(pack_bf2(v.x, v.y), pack_bf2(v.z, v.w));
            *(uint2*)&Bs[row * 72 + q * 4] = o;
        }
        __syncthreads();
#pragma unroll
        for (int ks = 0; ks < 4; ks++) {
            int k0 = ks * 16;
            uint32_t a[4][4], b[4][2];
#pragma unroll
            for (int mt = 0; mt < 4; mt++) {
                uint32_t ad = asb + ((wm * 64 + mt * 16 + (lane & 15)) * 72 +
                                     k0 + (lane >> 4) * 8) * 2;
                LDSM4(a[mt][0], a[mt][1], a[mt][2], a[mt][3], ad);
            }
#pragma unroll
            for (int nt = 0; nt < 4; nt++) {
                uint32_t bd = bsb + ((wn * 32 + nt * 8 + (lane & 7)) * 72 +
                                     k0 + ((lane >> 3) & 1) * 8) * 2;
                LDSM2(b[nt][0], b[nt][1], bd);
            }
#pragma unroll
            for (int mt = 0; mt < 4; mt++)
#pragma unroll
                for (int nt = 0; nt < 4; nt++)
                    MMA16816(acc[mt][nt], a[mt], b[nt]);
        }
    }
    __syncthreads();

    int tm = lane >> 2, tp = lane & 3;
#pragma unroll
    for (int mt = 0; mt < 4; mt++)
#pragma unroll
        for (int nt = 0; nt < 4; nt++) {
            int row = wm * 64 + mt * 16 + tm;
            int colp = wn * 16 + nt * 4 + tp;
            int c = colp * 2;
            unsigned short u0, u1;
            PACKF8(u0, acc[mt][nt][0] + biasS[c], acc[mt][nt][1] + biasS[c + 1]);
            PACKF8(u1, acc[mt][nt][2] + biasS[c], acc[mt][nt][3] + biasS[c + 1]);
            Cs[row * 72 + colp] = u0;
            Cs[(row + 8) * 72 + colp] = u1;
        }
    __syncthreads();
#pragma unroll
    for (int j = 0; j < 4; j++) {
        int lin = tid + 256 * j;
        int row = lin >> 3, q = lin & 7;
        int gn = n0 + row;
        if (gn < NN) {
            uint4 v = *(uint4*)&Cs[row * 72 + q * 8];
            ((uint4*)g_Wxf8)[(size_t)gn * 16 + (c0 >> 4) + q] = v;
        }
    }
}

// ---------------- K4abc: parallel exclusive scan (+1 self-loop folded) -----
__global__ __launch_bounds__(1024) void k_scan1() {
    __shared__ int wsum[32];
    int tid = threadIdx.x, lane = tid & 31, wid = tid >> 5;
    int i = blockIdx.x * 1024 + tid;
    int v = 0;
    if (i < NN) {
        v = g_cnt[i] + 1;        // +1 = self loop slot
        g_cnt[i] = 0;            // reset for next replay
    }
    int s = v;
#pragma unroll
    for (int o = 1; o < 32; o <<= 1) {
        int t = __shfl_up_sync(0xffffffffu, s, o);
        if (lane >= o) s += t;
    }
    if (lane == 31) wsum[wid] = s;
    __syncthreads();
    if (wid == 0) {
        int ws = wsum[lane];
#pragma unroll
        for (int o = 1; o < 32; o <<= 1) {
            int t = __shfl_up_sync(0xffffffffu, ws, o);
            if (lane >= o) ws += t;
        }
        wsum[lane] = ws;
    }
    __syncthreads();
    int incl = s + (wid > 0 ? wsum[wid - 1] : 0);
    if (i < NN) { g_rowptr[i + 1] = incl; g_cur[i] = incl - v; }
    if (tid == 1023) g_bsum[blockIdx.x] = incl;
}
__global__ void k_scan2() {       // 64 threads; also zeroes colsum
    int tid = threadIdx.x, lane = tid & 31, wid = tid >> 5;
    __shared__ int w0;
    for (int c = tid; c < CC; c += 64) g_colsum[c] = 0.f;
    int v = (tid < SCB) ? g_bsum[tid] : 0;
    int s = v;
#pragma unroll
    for (int o = 1; o < 32; o <<= 1) {
        int t = __shfl_up_sync(0xffffffffu, s, o);
        if (lane >= o) s += t;
    }
    if (tid == 31) w0 = s;
    __syncthreads();
    if (wid == 1) s += w0;
    if (tid < SCB) g_bsum[tid] = s - v;   // exclusive
}
__global__ __launch_bounds__(1024) void k_scan3() {
    int off = g_bsum[blockIdx.x];
    int i = blockIdx.x * 1024 + threadIdx.x;
    if (i < NN) { g_rowptr[i + 1] += off; g_cur[i] += off; }
    if (i == 0) g_rowptr[0] = 0;
}

// ---------------- F2: scatter ∥ scores --------------------------------------
__global__ __launch_bounds__(256) void k_f2(const float* __restrict__ aw,
                                            const float* __restrict__ ab,
                                            const int* __restrict__ ei) {
    int tid = threadIdx.x;
    if (blockIdx.x < F2_SCAT) {
        int i = blockIdx.x * 256 + tid;
        if (i < EE / 2) {
            int2 s2 = *(const int2*)&ei[2 * i];
            int2 d2 = *(const int2*)&ei[EE + 2 * i];
            int pa = atomicAdd(&g_cur[clampi(d2.x)], 1);
            int pb = atomicAdd(&g_cur[clampi(d2.y)], 1);
            if (pa < ETOT) g_csr[pa] = clampi(s2.x);
            if (pb < ETOT) g_csr[pb] = clampi(s2.y);
        } else {
            int n = i - EE / 2;
            if (n < NN) {
                int pos = atomicAdd(&g_cur[n], 1);
                if (pos < ETOT) g_csr[pos] = n;
            }
        }
        return;
    }
    int n = ((blockIdx.x - F2_SCAT) << 3) + (tid >> 5);
    int lane = tid & 31;
    if (n >= NN) return;
    int h = lane >> 3;
    int dd = (lane & 7) * 8;
    uint2 u = g_Wxf8[(size_t)n * 32 + lane];
    __half2 h0, h1, h2, h3;
    f8_to_f16x2(u.x, h0, h1);
    f8_to_f16x2(u.y, h2, h3);
    float2 p0 = __half22float2(h0), p1 = __half22float2(h1);
    float2 p2 = __half22float2(h2), p3 = __half22float2(h3);
    float f[8] = {p0.x, p0.y, p1.x, p1.y, p2.x, p2.y, p3.x, p3.y};
    const float* ai = aw + h * 128 + dd;
    const float* aj = ai + 64;
    float va = 0.f, vb = 0.f;
#pragma unroll
    for (int j = 0; j < 8; j++) { va += f[j] * ai[j]; vb += f[j] * aj[j]; }
#pragma unroll
    for (int o = 4; o; o >>= 1) {
        va += __shfl_xor_sync(0xffffffffu, va, o);
        vb += __shfl_xor_sync(0xffffffffu, vb, o);
    }
    if ((lane & 7) == 0) {
        g_sif[n * 4 + h] = (va + ab[h]) * LOG2E;
        g_sjf[n * 4 + h] = vb * LOG2E;
    }
}

// ---------------- K6: edge softmax + fp8 gather, 4-edge pipeline -----------
// Same warp/node mapping as R9; pipeline widened 2 -> 4 edges per iteration
// (~12 loads in flight) to close the latency-exposure gap toward the L2 floor.
__global__ __launch_bounds__(256) void k_agg() {
    int n = (blockIdx.x << 3) + (threadIdx.x >> 5);
    int lane = threadIdx.x & 31;
    if (n >= NN) return;
    int h = lane >> 3;
    int s = g_rowptr[n], en = g_rowptr[n + 1];
    float si = g_sif[n * 4 + h];

    __half2 acc0 = __float2half2_rn(0.f), acc1 = acc0, acc2 = acc0, acc3 = acc0;
    float den = 0.f;

    int src[4];
    float sj[4];
    uint2 u[4];
    int s0 = g_csr[s];
#pragma unroll
    for (int q = 0; q < 4; q++) {
        src[q] = (s + q < en) ? ((q == 0) ? s0 : g_csr[s + q]) : s0;
        sj[q] = g_sjf[src[q] * 4 + h];
        u[q] = g_Wxf8[(size_t)src[q] * 32 + lane];
    }

    for (int e = s; e < en; e += 4) {
        int nsrc[4];
        float nsj[4];
        uint2 nu[4];
#pragma unroll
        for (int q = 0; q < 4; q++) {
            nsrc[q] = (e + 4 + q < en) ? g_csr[e + 4 + q] : src[0];
            nsj[q] = g_sjf[nsrc[q] * 4 + h];
            nu[q] = g_Wxf8[(size_t)nsrc[q] * 32 + lane];
        }
#pragma unroll
        for (int q = 0; q < 4; q++) {
            if (e + q < en) {
                float t = si + sj[q];
                t = fmaxf(t, NEG * t);
                float c; EX2A(c, t);
                den += c;
                __half2 ch = __float2half2_rn(c);
                __half2 w0, w1, w2, w3;
                f8_to_f16x2(u[q].x, w0, w1);
                f8_to_f16x2(u[q].y, w2, w3);
                acc0 = __hfma2(ch, w0, acc0);
                acc1 = __hfma2(ch, w1, acc1);
                acc2 = __hfma2(ch, w2, acc2);
                acc3 = __hfma2(ch, w3, acc3);
            }
        }
#pragma unroll
        for (int q = 0; q < 4; q++) { src[q] = nsrc[q]; sj[q] = nsj[q]; u[q] = nu[q]; }
    }
    float inv = 1.f / den;
    float2 f0 = __half22float2(acc0);
    float2 f1 = __half22float2(acc1);
    float2 f2 = __half22float2(acc2);
    float2 f3 = __half22float2(acc3);
    unsigned p0, p1, p2, p3;
    PACKBF(p0, __expf(f0.x * inv), __expf(f0.y * inv));
    PACKBF(p1, __expf(f1.x * inv), __expf(f1.y * inv));
    PACKBF(p2, __expf(f2.x * inv), __expf(f2.y * inv));
    PACKBF(p3, __expf(f3.x * inv), __expf(f3.y * inv));
    g_aggh4[(size_t)n * 32 + lane] = make_uint4(p0, p1, p2, p3);
}

// ---------------- K7: column sum of E (250 blocks x 200 rows) --------------
__global__ __launch_bounds__(256) void k_colsum() {
    const unsigned* Ah = (const unsigned*)g_aggh4;
    int tid = threadIdx.x;
    int c2 = tid & 127;                // uint index = column pair
    int g = tid >> 7;
    int n0 = blockIdx.x * 200;
    float s0 = 0.f, s1 = 0.f;
    for (int r = g; r < 200; r += 2) {
        unsigned u = Ah[(size_t)(n0 + r) * 128 + c2];
        s0 += bflo(u);
        s1 += bfhi(u);
    }
    atomicAdd(&g_colsum[c2 * 2], s0);
    atomicAdd(&g_colsum[c2 * 2 + 1], s1);
}

// ---------------- K8: out = (E*siv) @ Wo^T + b  (bf16 mma.sync) ------------
__global__ __launch_bounds__(256) void k_out(const float* __restrict__ Wo,
                                             const float* __restrict__ Wob,
                                             float* __restrict__ out) {
    __shared__ __align__(16) char smbuf[34816];
    __shared__ float sivS[CC];
    __nv_bfloat16* As = (__nv_bfloat16*)smbuf;            // [128][72]
    __nv_bfloat16* Bs = (__nv_bfloat16*)(smbuf + 18432);  // [64][72]
    float* Csf = (float*)smbuf;                           // overlay
    int tid = threadIdx.x, lane = tid & 31, wid = tid >> 5;
    int n0 = blockIdx.x * 128;
    int wm = wid & 3, wn = wid >> 2;
    uint32_t asb = (uint32_t)__cvta_generic_to_shared(As);
    uint32_t bsb = (uint32_t)__cvta_generic_to_shared(Bs);

    sivS[tid] = 1.f / g_colsum[tid];

    float acc[2][4][4];
#pragma unroll
    for (int mt = 0; mt < 2; mt++)
#pragma unroll
        for (int nt = 0; nt < 4; nt++)
#pragma unroll
            for (int r = 0; r < 4; r++) acc[mt][nt][r] = 0.f;

    for (int cb = 0; cb < CC; cb += 64) {
        __syncthreads();
#pragma unroll
        for (int j = 0; j < 4; j++) {
            int lin = tid + 256 * j;
            int row = lin >> 3, q = lin & 7;
            int gn = n0 + row; if (gn >= NN) gn = NN - 1;
            uint4 u = g_aggh4[(size_t)gn * 32 + (cb >> 3) + q];
            unsigned ua[4] = {u.x, u.y, u.z, u.w};
            unsigned ou[4];
#pragma unroll
            for (int i = 0; i < 4; i++) {
                int c = cb + q * 8 + 2 * i;
                ou[i] = pack_bf2(bflo(ua[i]) * sivS[c], bfhi(ua[i]) * sivS[c + 1]);
            }
            *(uint4*)&As[row * 72 + q * 8] = make_uint4(ou[0], ou[1], ou[2], ou[3]);
        }
#pragma unroll
        for (int j = 0; j < 4; j++) {
            int lin = tid + 256 * j;
            int row = lin >> 4, q = lin & 15;
            float4 v = *(const float4*)&Wo[(size_t)row * CC + cb + q * 4];
            uint2 o = make_uint2(pack_bf2(v.x, v.y), pack_bf2(v.z, v.w));
            *(uint2*)&Bs[row * 72 + q * 4] = o;
        }
        __syncthreads();
#pragma unroll
        for (int ks = 0; ks < 4; ks++) {
            int k0 = ks * 16;
            uint32_t a[2][4], b[4][2];
#pragma unroll
            for (int mt = 0; mt < 2; mt++) {
                uint32_t ad = asb + ((wm * 32 + mt * 16 + (lane & 15)) * 72 +
                                     k0 + (lane >> 4) * 8) * 2;
                LDSM4(a[mt][0], a[mt][1], a[mt][2], a[mt][3], ad);
            }
#pragma unroll
            for (int nt = 0; nt < 4; nt++) {
                uint32_t bd = bsb + ((wn * 32 + nt * 8 + (lane & 7)) * 72 +
                                     k0 + ((lane >> 3) & 1) * 8) * 2;
                LDSM2(b[nt][0], b[nt][1], bd);
            }
#pragma unroll
            for (int mt = 0; mt < 2; mt++)
#pragma unroll
                for (int nt = 0; nt < 4; nt++)
                    MMA16816(acc[mt][nt], a[mt], b[nt]);
        }
    }
    __syncthreads();

    int tm = lane >> 2, tp = lane & 3;
#pragma unroll
    for (int mt = 0; mt < 2; mt++)
#pragma unroll
        for (int nt = 0; nt < 4; nt++) {
            int row = wm * 32 + mt * 16 + tm;
            int col = wn * 32 + nt * 8 + 2 * tp;
            Csf[row * 68 + col] = acc[mt][nt][0];
            Csf[row * 68 + col + 1] = acc[mt][nt][1];
            Csf[(row + 8) * 68 + col] = acc[mt][nt][2];
            Csf[(row + 8) * 68 + col + 1] = acc[mt][nt][3];
        }
    __syncthreads();
#pragma unroll
    for (int j = 0; j < 8; j++) {
        int lin = tid + 256 * j;
        int row = lin >> 4, q = lin & 15;
        int gn = n0 + row;
        if (gn < NN) {
            float4 v = *(float4*)&Csf[row * 68 + q * 4];
            float4 b = *(const float4*)&Wob[q * 4];
            float4 o = {v.x + b.x, v.y + b.y, v.z + b.z, v.w + b.w};
            *(float4*)&out[(size_t)gn * 64 + q * 4] = o;
        }
    }
}

// ---------------- launch ----------------------------------------------------
extern "C" void kernel_launch(void* const* d_in, const int* in_sizes, int n_in,
                              void* d_out, int out_size) {
    (void)out_size;
    const void* p[8];
    for (int j = 0; j < 8; j++) p[j] = (j < n_in) ? d_in[j] : 0;
    const int want[8] = {2 * EE, NN * DXX, KH * DHH * DXX, KH * DHH,
                         KH * 2 * DHH, KH, DHH * CC, DHH};
    for (int j = 0; j < 8; j++)
        for (int i = 0; i < n_in; i++)
            if (in_sizes[i] == want[j]) { p[j] = d_in[i]; break; }

    const int*   ei  = (const int*)p[0];
    const float* x   = (const float*)p[1];
    const float* Ww  = (const float*)p[2];
    const float* Wb  = (const float*)p[3];
    const float* aw  = (const float*)p[4];
    const float* ab  = (const float*)p[5];
    const float* Wo  = (const float*)p[6];
    const float* Wob = (const float*)p[7];
    float* out = (float*)d_out;

    k_f1<<<F1_WX + F1_HIST, 256>>>(x, Ww, Wb, ei);
    k_scan1<<<SCB, 1024>>>();
    k_scan2<<<1, 64>>>();
    k_scan3<<<SCB, 1024>>>();
    k_f2<<<F2_SCAT + F2_SCORE, 256>>>(aw, ab, ei);
    k_agg<<<(NN + 7) / 8, 256>>>();
    k_colsum<<<250, 256>>>();
    k_out<<<391, 256>>>(Wo, Wob, out);
}

// round 14
// speedup vs baseline: 1.3102x; 1.1284x over previous
#include <cuda_runtime.h>
#include <cuda_bf16.h>
#include <cuda_fp16.h>
#include <cstdint>

typedef unsigned long long ull;

#define NN 50000
#define EE 1600000
#define ETOT 1650000
#define KH 4
#define DHH 64
#define DXX 128
#define CC 256          // KH*DHH
#define NEG 0.01f
#define SCB 49          // scan blocks (49*1024 >= NN)
#define LOG2E 1.44269504f

// f1: blocks [0,782) = wx tiles (+ fused scores), then hist (2 edges/thread)
#define F1_WX 782
#define F1_HIST 3125
// f2: scatter only (2 edges/thread + self loops)
#define F2_SCAT 3321

// ---------------- scratch (static device globals; zero-init at load) --------
__device__ uint2 g_Wxf8[NN * 32];        // 12.8 MB  fp8 Wx[n][c] (256B/row)
__device__ uint4 g_aggh4[NN * 32];       // 25.6 MB  bf16 E = exp(agg)
__device__ float g_sif[NN * KH];         // (si + ab) * log2e, per head
__device__ float g_sjf[NN * KH];         // sj * log2e, per head
__device__ int g_cnt[NN];                // zero-init; re-zeroed by scan1
__device__ int g_rowptr[NN + 1];
__device__ int g_cur[NN];
__device__ int g_bsum[64];
__device__ int g_csr[ETOT];              // src indices grouped by dst
__device__ float g_colsum[CC];           // re-zeroed by scan2

// ---------------- helpers ---------------------------------------------------
__device__ __forceinline__ float bflo(unsigned u) { return __uint_as_float(u << 16); }
__device__ __forceinline__ float bfhi(unsigned u) { return __uint_as_float(u & 0xffff0000u); }
__device__ __forceinline__ int clampi(int v) {
    return v < 0 ? 0 : (v >= NN ? NN - 1 : v);
}

#define PACKBF(r, lo, hi) asm("cvt.rn.bf16x2.f32 %0, %1, %2;" : "=r"(r) : "f"(hi), "f"(lo))
#define PACKF8(r, lo, hi) \
    asm("cvt.rn.satfinite.e4m3x2.f32 %0, %1, %2;" : "=h"(r) : "f"(hi), "f"(lo))
#define UNPF8(d, s) asm("cvt.rn.f16x2.e4m3x2 %0, %1;" : "=r"(d) : "h"(s))
#define EX2A(d, s) asm("ex2.approx.ftz.f32 %0, %1;" : "=f"(d) : "f"(s))

__device__ __forceinline__ void f8_to_f16x2(unsigned u32v, __half2& lo, __half2& hi) {
    unsigned short sl = (unsigned short)(u32v & 0xffffu);
    unsigned short sh = (unsigned short)(u32v >> 16);
    unsigned a, b;
    UNPF8(a, sl);
    UNPF8(b, sh);
    lo = *(__half2*)&a;
    hi = *(__half2*)&b;
}

#define LDSM4(r0, r1, r2, r3, a) asm volatile( \
    "ldmatrix.sync.aligned.m8n8.x4.shared.b16 {%0,%1,%2,%3}, [%4];" \
    : "=r"(r0), "=r"(r1), "=r"(r2), "=r"(r3) : "r"(a))
#define LDSM2(r0, r1, a) asm volatile( \
    "ldmatrix.sync.aligned.m8n8.x2.shared.b16 {%0,%1}, [%2];" \
    : "=r"(r0), "=r"(r1) : "r"(a))
#define MMA16816(d, a, b) asm volatile( \
    "mma.sync.aligned.m16n8k16.row.col.f32.bf16.bf16.f32 " \
    "{%0,%1,%2,%3}, {%4,%5,%6,%7}, {%8,%9}, {%0,%1,%2,%3};" \
    : "+f"((d)[0]), "+f"((d)[1]), "+f"((d)[2]), "+f"((d)[3]) \
    : "r"((a)[0]), "r"((a)[1]), "r"((a)[2]), "r"((a)[3]), "r"((b)[0]), "r"((b)[1]))

__device__ __forceinline__ unsigned pack_bf2(float lo, float hi) {
    unsigned r; PACKBF(r, lo, hi); return r;
}

// ---------------- F1: Wx GEMM + fused scores ∥ degree hist ------------------
__global__ __launch_bounds__(256) void k_f1(const float* __restrict__ x,
                                            const float* __restrict__ Ww,
                                            const float* __restrict__ Wb,
                                            const float* __restrict__ aw,
                                            const float* __restrict__ ab,
                                            const int* __restrict__ ei) {
    __shared__ __align__(16) char smbuf[36864];
    __shared__ float biasS[128];
    int tid = threadIdx.x, lane = tid & 31, wid = tid >> 5;

    if (blockIdx.x >= F1_WX) {
        // ---- hist role: 2 edges/thread ----
        int i = (blockIdx.x - F1_WX) * 256 + tid;
        if (i < EE / 2) {
            int2 d2 = *(const int2*)&ei[EE + 2 * i];
            atomicAdd(&g_cnt[clampi(d2.x)], 1);
            atomicAdd(&g_cnt[clampi(d2.y)], 1);
        }
        return;
    }

    __nv_bfloat16* As = (__nv_bfloat16*)smbuf;            // [128][72]
    __nv_bfloat16* Bs = (__nv_bfloat16*)(smbuf + 18432);  // [128][72]
    unsigned short* Cs = (unsigned short*)smbuf;          // overlay
    int n0 = (blockIdx.x >> 1) * 128, c0 = (blockIdx.x & 1) * 128;
    int wm = wid >> 2, wn = wid & 3;
    uint32_t asb = (uint32_t)__cvta_generic_to_shared(As);
    uint32_t bsb = (uint32_t)__cvta_generic_to_shared(Bs);

    if (tid < 128) biasS[tid] = Wb[c0 + tid];

    float acc[4][4][4];
#pragma unroll
    for (int mt = 0; mt < 4; mt++)
#pragma unroll
        for (int nt = 0; nt < 4; nt++)
#pragma unroll
            for (int r = 0; r < 4; r++) acc[mt][nt][r] = 0.f;

    for (int kc = 0; kc < DXX; kc += 64) {
        __syncthreads();
#pragma unroll
        for (int j = 0; j < 8; j++) {
            int lin = tid + 256 * j;
            int row = lin >> 4, q = lin & 15;
            int gn = n0 + row; if (gn >= NN) gn = NN - 1;
            float4 v = *(const float4*)&x[(size_t)gn * DXX + kc + q * 4];
            uint2 o = make_uint2(pack_bf2(v.x, v.y), pack_bf2(v.z, v.w));
            *(uint2*)&As[row * 72 + q * 4] = o;
        }
#pragma unroll
        for (int j = 0; j < 8; j++) {
            int lin = tid + 256 * j;
            int row = lin >> 4, q = lin & 15;
            float4 v = *(const float4*)&Ww[(size_t)(c0 + row) * DXX + kc + q * 4];
            uint2 o = make_uint2(pack_bf2(v.x, v.y), pack_bf2(v.z, v.w));
            *(uint2*)&Bs[row * 72 + q * 4] = o;
        }
        __syncthreads();
#pragma unroll
        for (int ks = 0; ks < 4; ks++) {
            int k0 = ks * 16;
            uint32_t a[4][4], b[4][2];
#pragma unroll
            for (int mt = 0; mt < 4; mt++) {
                uint32_t ad = asb + ((wm * 64 + mt * 16 + (lane & 15)) * 72 +
                                     k0 + (lane >> 4) * 8) * 2;
                LDSM4(a[mt][0], a[mt][1], a[mt][2], a[mt][3], ad);
            }
#pragma unroll
            for (int nt = 0; nt < 4; nt++) {
                uint32_t bd = bsb + ((wn * 32 + nt * 8 + (lane & 7)) * 72 +
                                     k0 + ((lane >> 3) & 1) * 8) * 2;
                LDSM2(b[nt][0], b[nt][1], bd);
            }
#pragma unroll
            for (int mt = 0; mt < 4; mt++)
#pragma unroll
                for (int nt = 0; nt < 4; nt++)
                    MMA16816(acc[mt][nt], a[mt], b[nt]);
        }
    }
    __syncthreads();

    // epilogue: bias + fp8 pack into smem
    int tm = lane >> 2, tp = lane & 3;
#pragma unroll
    for (int mt = 0; mt < 4; mt++)
#pragma unroll
        for (int nt = 0; nt < 4; nt++) {
            int row = wm * 64 + mt * 16 + tm;
            int colp = wn * 16 + nt * 4 + tp;
            int c = colp * 2;
            unsigned short u0, u1;
            PACKF8(u0, acc[mt][nt][0] + biasS[c], acc[mt][nt][1] + biasS[c + 1]);
            PACKF8(u1, acc[mt][nt][2] + biasS[c], acc[mt][nt][3] + biasS[c + 1]);
            Cs[row * 72 + colp] = u0;
            Cs[(row + 8) * 72 + colp] = u1;
        }
    __syncthreads();
    // coalesced fp8 stores
#pragma unroll
    for (int j = 0; j < 4; j++) {
        int lin = tid + 256 * j;
        int row = lin >> 3, q = lin & 7;
        int gn = n0 + row;
        if (gn < NN) {
            uint4 v = *(uint4*)&Cs[row * 72 + q * 8];
            ((uint4*)g_Wxf8)[(size_t)gn * 16 + (c0 >> 4) + q] = v;
        }
    }

    // fused scores: this block holds 2 complete heads (cols c0..c0+127).
    // thread t handles (row = t&127, head = c0/64 + t>>7).
    {
        int row = tid & 127, hh = tid >> 7;
        int head = (c0 >> 6) + hh;
        int gn = n0 + row;
        if (gn < NN) {
            const unsigned short* cr = &Cs[row * 72 + hh * 32];
            const float* ai = aw + head * 128;
            const float* aj = ai + 64;
            float va = 0.f, vb = 0.f;
#pragma unroll
            for (int q = 0; q < 32; q++) {
                unsigned r; UNPF8(r, cr[q]);
                float2 f = __half22float2(*(__half2*)&r);
                va += f.x * ai[2 * q] + f.y * ai[2 * q + 1];
                vb += f.x * aj[2 * q] + f.y * aj[2 * q + 1];
            }
            g_sif[gn * 4 + head] = (va + ab[head]) * LOG2E;
            g_sjf[gn * 4 + head] = vb * LOG2E;
        }
    }
}

// ---------------- K4abc: parallel exclusive scan (+1 self-loop folded) -----
__global__ __launch_bounds__(1024) void k_scan1() {
    __shared__ int wsum[32];
    int tid = threadIdx.x, lane = tid & 31, wid = tid >> 5;
    int i = blockIdx.x * 1024 + tid;
    int v = 0;
    if (i < NN) {
        v = g_cnt[i] + 1;        // +1 = self loop slot
        g_cnt[i] = 0;            // reset for next replay
    }
    int s = v;
#pragma unroll
    for (int o = 1; o < 32; o <<= 1) {
        int t = __shfl_up_sync(0xffffffffu, s, o);
        if (lane >= o) s += t;
    }
    if (lane == 31) wsum[wid] = s;
    __syncthreads();
    if (wid == 0) {
        int ws = wsum[lane];
#pragma unroll
        for (int o = 1; o < 32; o <<= 1) {
            int t = __shfl_up_sync(0xffffffffu, ws, o);
            if (lane >= o) ws += t;
        }
        wsum[lane] = ws;
    }
    __syncthreads();
    int incl = s + (wid > 0 ? wsum[wid - 1] : 0);
    if (i < NN) { g_rowptr[i + 1] = incl; g_cur[i] = incl - v; }
    if (tid == 1023) g_bsum[blockIdx.x] = incl;
}
__global__ void k_scan2() {       // 64 threads; also zeroes colsum
    int tid = threadIdx.x, lane = tid & 31, wid = tid >> 5;
    __shared__ int w0;
    for (int c = tid; c < CC; c += 64) g_colsum[c] = 0.f;
    int v = (tid < SCB) ? g_bsum[tid] : 0;
    int s = v;
#pragma unroll
    for (int o = 1; o < 32; o <<= 1) {
        int t = __shfl_up_sync(0xffffffffu, s, o);
        if (lane >= o) s += t;
    }
    if (tid == 31) w0 = s;
    __syncthreads();
    if (wid == 1) s += w0;
    if (tid < SCB) g_bsum[tid] = s - v;   // exclusive
}
__global__ __launch_bounds__(1024) void k_scan3() {
    int off = g_bsum[blockIdx.x];
    int i = blockIdx.x * 1024 + threadIdx.x;
    if (i < NN) { g_rowptr[i + 1] += off; g_cur[i] += off; }
    if (i == 0) g_rowptr[0] = 0;
}

// ---------------- F2: scatter only ------------------------------------------
__global__ __launch_bounds__(256) void k_f2(const int* __restrict__ ei) {
    int tid = threadIdx.x;
    int i = blockIdx.x * 256 + tid;
    if (i < EE / 2) {
        int2 s2 = *(const int2*)&ei[2 * i];
        int2 d2 = *(const int2*)&ei[EE + 2 * i];
        int pa = atomicAdd(&g_cur[clampi(d2.x)], 1);
        int pb = atomicAdd(&g_cur[clampi(d2.y)], 1);
        if (pa < ETOT) g_csr[pa] = clampi(s2.x);
        if (pb < ETOT) g_csr[pb] = clampi(s2.y);
    } else {
        int n = i - EE / 2;
        if (n < NN) {
            int pos = atomicAdd(&g_cur[n], 1);
            if (pos < ETOT) g_csr[pos] = n;
        }
    }
}

// ---------------- K6: edge softmax + fp8 gather, depth-2 pipe (R9) ---------
__global__ __launch_bounds__(256) void k_agg() {
    int n = (blockIdx.x << 3) + (threadIdx.x >> 5);
    int lane = threadIdx.x & 31;
    if (n >= NN) return;
    int h = lane >> 3;
    int s = g_rowptr[n], en = g_rowptr[n + 1];
    float si = g_sif[n * 4 + h];

    __half2 acc0 = __float2half2_rn(0.f), acc1 = acc0, acc2 = acc0, acc3 = acc0;
    float den = 0.f;

    int srcA = g_csr[s];
    int srcB = (s + 1 < en) ? g_csr[s + 1] : srcA;
    float sjA = g_sjf[srcA * 4 + h], sjB = g_sjf[srcB * 4 + h];
    uint2 uA = g_Wxf8[(size_t)srcA * 32 + lane];
    uint2 uB = g_Wxf8[(size_t)srcB * 32 + lane];

    for (int e = s; e < en; e += 2) {
        int nA = (e + 2 < en) ? g_csr[e + 2] : srcA;
        int nB = (e + 3 < en) ? g_csr[e + 3] : srcA;
        float sjAn = g_sjf[nA * 4 + h];
        uint2 uAn = g_Wxf8[(size_t)nA * 32 + lane];
        float sjBn = g_sjf[nB * 4 + h];
        uint2 uBn = g_Wxf8[(size_t)nB * 32 + lane];

        {
            float t = si + sjA;
            t = fmaxf(t, NEG * t);
            float c; EX2A(c, t);
            den += c;
            __half2 ch = __float2half2_rn(c);
            __half2 w0, w1, w2, w3;
            f8_to_f16x2(uA.x, w0, w1);
            f8_to_f16x2(uA.y, w2, w3);
            acc0 = __hfma2(ch, w0, acc0);
            acc1 = __hfma2(ch, w1, acc1);
            acc2 = __hfma2(ch, w2, acc2);
            acc3 = __hfma2(ch, w3, acc3);
        }
        if (e + 1 < en) {
            float t = si + sjB;
            t = fmaxf(t, NEG * t);
            float c; EX2A(c, t);
            den += c;
            __half2 ch = __float2half2_rn(c);
            __half2 w0, w1, w2, w3;
            f8_to_f16x2(uB.x, w0, w1);
            f8_to_f16x2(uB.y, w2, w3);
            acc0 = __hfma2(ch, w0, acc0);
            acc1 = __hfma2(ch, w1, acc1);
            acc2 = __hfma2(ch, w2, acc2);
            acc3 = __hfma2(ch, w3, acc3);
        }
        sjA = sjAn; uA = uAn; sjB = sjBn; uB = uBn;
    }
    float inv = 1.f / den;
    float2 f0 = __half22float2(acc0);
    float2 f1 = __half22float2(acc1);
    float2 f2 = __half22float2(acc2);
    float2 f3 = __half22float2(acc3);
    unsigned p0, p1, p2, p3;
    PACKBF(p0, __expf(f0.x * inv), __expf(f0.y * inv));
    PACKBF(p1, __expf(f1.x * inv), __expf(f1.y * inv));
    PACKBF(p2, __expf(f2.x * inv), __expf(f2.y * inv));
    PACKBF(p3, __expf(f3.x * inv), __expf(f3.y * inv));
    g_aggh4[(size_t)n * 32 + lane] = make_uint4(p0, p1, p2, p3);
}

// ---------------- K7: column sum of E (250 blocks x 200 rows) --------------
__global__ __launch_bounds__(256) void k_colsum() {
    const unsigned* Ah = (const unsigned*)g_aggh4;
    int tid = threadIdx.x;
    int c2 = tid & 127;                // uint index = column pair
    int g = tid >> 7;
    int n0 = blockIdx.x * 200;
    float s0 = 0.f, s1 = 0.f;
    for (int r = g; r < 200; r += 2) {
        unsigned u = Ah[(size_t)(n0 + r) * 128 + c2];
        s0 += bflo(u);
        s1 += bfhi(u);
    }
    atomicAdd(&g_colsum[c2 * 2], s0);
    atomicAdd(&g_colsum[c2 * 2 + 1], s1);
}

// ---------------- K8: out = (E*siv) @ Wo^T + b  (bf16 mma.sync) ------------
__global__ __launch_bounds__(256) void k_out(const float* __restrict__ Wo,
                                             const float* __restrict__ Wob,
                                             float* __restrict__ out) {
    __shared__ __align__(16) char smbuf[34816];
    __shared__ float sivS[CC];
    __nv_bfloat16* As = (__nv_bfloat16*)smbuf;            // [128][72]
    __nv_bfloat16* Bs = (__nv_bfloat16*)(smbuf + 18432);  // [64][72]
    float* Csf = (float*)smbuf;                           // overlay
    int tid = threadIdx.x, lane = tid & 31, wid = tid >> 5;
    int n0 = blockIdx.x * 128;
    int wm = wid & 3, wn = wid >> 2;
    uint32_t asb = (uint32_t)__cvta_generic_to_shared(As);
    uint32_t bsb = (uint32_t)__cvta_generic_to_shared(Bs);

    sivS[tid] = 1.f / g_colsum[tid];

    float acc[2][4][4];
#pragma unroll
    for (int mt = 0; mt < 2; mt++)
#pragma unroll
        for (int nt = 0; nt < 4; nt++)
#pragma unroll
            for (int r = 0; r < 4; r++) acc[mt][nt][r] = 0.f;

    for (int cb = 0; cb < CC; cb += 64) {
        __syncthreads();
#pragma unroll
        for (int j = 0; j < 4; j++) {
            int lin = tid + 256 * j;
            int row = lin >> 3, q = lin & 7;
            int gn = n0 + row; if (gn >= NN) gn = NN - 1;
            uint4 u = g_aggh4[(size_t)gn * 32 + (cb >> 3) + q];
            unsigned ua[4] = {u.x, u.y, u.z, u.w};
            unsigned ou[4];
#pragma unroll
            for (int i = 0; i < 4; i++) {
                int c = cb + q * 8 + 2 * i;
                ou[i] = pack_bf2(bflo(ua[i]) * sivS[c], bfhi(ua[i]) * sivS[c + 1]);
            }
            *(uint4*)&As[row * 72 + q * 8] = make_uint4(ou[0], ou[1], ou[2], ou[3]);
        }
#pragma unroll
        for (int j = 0; j < 4; j++) {
            int lin = tid + 256 * j;
            int row = lin >> 4, q = lin & 15;
            float4 v = *(const float4*)&Wo[(size_t)row * CC + cb + q * 4];
            uint2 o = make_uint2(pack_bf2(v.x, v.y), pack_bf2(v.z, v.w));
            *(uint2*)&Bs[row * 72 + q * 4] = o;
        }
        __syncthreads();
#pragma unroll
        for (int ks = 0; ks < 4; ks++) {
            int k0 = ks * 16;
            uint32_t a[2][4], b[4][2];
#pragma unroll
            for (int mt = 0; mt < 2; mt++) {
                uint32_t ad = asb + ((wm * 32 + mt * 16 + (lane & 15)) * 72 +
                                     k0 + (lane >> 4) * 8) * 2;
                LDSM4(a[mt][0], a[mt][1], a[mt][2], a[mt][3], ad);
            }
#pragma unroll
            for (int nt = 0; nt < 4; nt++) {
                uint32_t bd = bsb + ((wn * 32 + nt * 8 + (lane & 7)) * 72 +
                                     k0 + ((lane >> 3) & 1) * 8) * 2;
                LDSM2(b[nt][0], b[nt][1], bd);
            }
#pragma unroll
            for (int mt = 0; mt < 2; mt++)
#pragma unroll
                for (int nt = 0; nt < 4; nt++)
                    MMA16816(acc[mt][nt], a[mt], b[nt]);
        }
    }
    __syncthreads();

    int tm = lane >> 2, tp = lane & 3;
#pragma unroll
    for (int mt = 0; mt < 2; mt++)
#pragma unroll
        for (int nt = 0; nt < 4; nt++) {
            int row = wm * 32 + mt * 16 + tm;
            int col = wn * 32 + nt * 8 + 2 * tp;
            Csf[row * 68 + col] = acc[mt][nt][0];
            Csf[row * 68 + col + 1] = acc[mt][nt][1];
            Csf[(row + 8) * 68 + col] = acc[mt][nt][2];
            Csf[(row + 8) * 68 + col + 1] = acc[mt][nt][3];
        }
    __syncthreads();
#pragma unroll
    for (int j = 0; j < 8; j++) {
        int lin = tid + 256 * j;
        int row = lin >> 4, q = lin & 15;
        int gn = n0 + row;
        if (gn < NN) {
            float4 v = *(float4*)&Csf[row * 68 + q * 4];
            float4 b = *(const float4*)&Wob[q * 4];
            float4 o = {v.x + b.x, v.y + b.y, v.z + b.z, v.w + b.w};
            *(float4*)&out[(size_t)gn * 64 + q * 4] = o;
        }
    }
}

// ---------------- launch ----------------------------------------------------
extern "C" void kernel_launch(void* const* d_in, const int* in_sizes, int n_in,
                              void* d_out, int out_size) {
    (void)out_size;
    const void* p[8];
    for (int j = 0; j < 8; j++) p[j] = (j < n_in) ? d_in[j] : 0;
    const int want[8] = {2 * EE, NN * DXX, KH * DHH * DXX, KH * DHH,
                         KH * 2 * DHH, KH, DHH * CC, DHH};
    for (int j = 0; j < 8; j++)
        for (int i = 0; i < n_in; i++)
            if (in_sizes[i] == want[j]) { p[j] = d_in[i]; break; }

    const int*   ei  = (const int*)p[0];
    const float* x   = (const float*)p[1];
    const float* Ww  = (const float*)p[2];
    const float* Wb  = (const float*)p[3];
    const float* aw  = (const float*)p[4];
    const float* ab  = (const float*)p[5];
    const float* Wo  = (const float*)p[6];
    const float* Wob = (const float*)p[7];
    float* out = (float*)d_out;

    k_f1<<<F1_WX + F1_HIST, 256>>>(x, Ww, Wb, aw, ab, ei);
    k_scan1<<<SCB, 1024>>>();
    k_scan2<<<1, 64>>>();
    k_scan3<<<SCB, 1024>>>();
    k_f2<<<F2_SCAT, 256>>>(ei);
    k_agg<<<(NN + 7) / 8, 256>>>();
    k_colsum<<<250, 256>>>();
    k_out<<<391, 256>>>(Wo, Wob, out);
}

// round 15
// speedup vs baseline: 1.3241x; 1.0106x over previous
#include <cuda_runtime.h>
#include <cuda_bf16.h>
#include <cuda_fp16.h>
#include <cstdint>

typedef unsigned long long ull;

#define NN 50000
#define EE 1600000
#define ETOT 1650000
#define KH 4
#define DHH 64
#define DXX 128
#define CC 256          // KH*DHH
#define NEG 0.01f
#define LOG2E 1.44269504f

// f1: blocks [0,782) = wx tiles (+ fused scores), then hist (2 edges/thread)
#define F1_WX 782
#define F1_HIST 3125
// f2: 49 scan blocks (1024 elems each, 4/thread) + scatter blocks
#define F2_SCAN 49
#define F2_SCAT 3321

// ---------------- scratch (static device globals; zero-init at load) --------
__device__ uint2 g_Wxf8[NN * 32];        // 12.8 MB  fp8 Wx[n][c] (256B/row)
__device__ uint4 g_aggh4[NN * 32];       // 25.6 MB  bf16 E = exp(agg)
__device__ float g_sif[NN * KH];         // (si + ab) * log2e, per head
__device__ float g_sjf[NN * KH];         // sj * log2e, per head
__device__ int g_cnt[NN];                // zero-init; re-zeroed by f2 scan
__device__ int g_rowptr[NN + 1];
__device__ int g_cur[NN];
__device__ unsigned g_bstat[64];         // packed READY|total; reset by k_agg
__device__ int g_done;                   // reset by k_agg
__device__ int g_csr[ETOT];              // src indices grouped by dst
__device__ float g_colsum[CC];           // zeroed by f2 scan block 0

// ---------------- helpers ---------------------------------------------------
__device__ __forceinline__ float bflo(unsigned u) { return __uint_as_float(u << 16); }
__device__ __forceinline__ float bfhi(unsigned u) { return __uint_as_float(u & 0xffff0000u); }
__device__ __forceinline__ int clampi(int v) {
    return v < 0 ? 0 : (v >= NN ? NN - 1 : v);
}
__device__ __forceinline__ int ld_acq(const int* p) {
    int v;
    asm volatile("ld.acquire.gpu.s32 %0, [%1];" : "=r"(v) : "l"(p));
    return v;
}

#define PACKBF(r, lo, hi) asm("cvt.rn.bf16x2.f32 %0, %1, %2;" : "=r"(r) : "f"(hi), "f"(lo))
#define PACKF8(r, lo, hi) \
    asm("cvt.rn.satfinite.e4m3x2.f32 %0, %1, %2;" : "=h"(r) : "f"(hi), "f"(lo))
#define UNPF8(d, s) asm("cvt.rn.f16x2.e4m3x2 %0, %1;" : "=r"(d) : "h"(s))
#define EX2A(d, s) asm("ex2.approx.ftz.f32 %0, %1;" : "=f"(d) : "f"(s))

__device__ __forceinline__ void f8_to_f16x2(unsigned u32v, __half2& lo, __half2& hi) {
    unsigned short sl = (unsigned short)(u32v & 0xffffu);
    unsigned short sh = (unsigned short)(u32v >> 16);
    unsigned a, b;
    UNPF8(a, sl);
    UNPF8(b, sh);
    lo = *(__half2*)&a;
    hi = *(__half2*)&b;
}

#define LDSM4(r0, r1, r2, r3, a) asm volatile( \
    "ldmatrix.sync.aligned.m8n8.x4.shared.b16 {%0,%1,%2,%3}, [%4];" \
    : "=r"(r0), "=r"(r1), "=r"(r2), "=r"(r3) : "r"(a))
#define LDSM2(r0, r1, a) asm volatile( \
    "ldmatrix.sync.aligned.m8n8.x2.shared.b16 {%0,%1}, [%2];" \
    : "=r"(r0), "=r"(r1) : "r"(a))
#define MMA16816(d, a, b) asm volatile( \
    "mma.sync.aligned.m16n8k16.row.col.f32.bf16.bf16.f32 " \
    "{%0,%1,%2,%3}, {%4,%5,%6,%7}, {%8,%9}, {%0,%1,%2,%3};" \
    : "+f"((d)[0]), "+f"((d)[1]), "+f"((d)[2]), "+f"((d)[3]) \
    : "r"((a)[0]), "r"((a)[1]), "r"((a)[2]), "r"((a)[3]), "r"((b)[0]), "r"((b)[1]))

__device__ __forceinline__ unsigned pack_bf2(float lo, float hi) {
    unsigned r; PACKBF(r, lo, hi); return r;
}

// ---------------- F1: Wx GEMM + fused scores ∥ degree hist ------------------
__global__ __launch_bounds__(256) void k_f1(const float* __restrict__ x,
                                            const float* __restrict__ Ww,
                                            const float* __restrict__ Wb,
                                            const float* __restrict__ aw,
                                            const float* __restrict__ ab,
                                            const int* __restrict__ ei) {
    __shared__ __align__(16) char smbuf[36864];
    __shared__ float biasS[128];
    int tid = threadIdx.x, lane = tid & 31, wid = tid >> 5;

    if (blockIdx.x >= F1_WX) {
        // ---- hist role: 2 edges/thread ----
        int i = (blockIdx.x - F1_WX) * 256 + tid;
        if (i < EE / 2) {
            int2 d2 = *(const int2*)&ei[EE + 2 * i];
            atomicAdd(&g_cnt[clampi(d2.x)], 1);
            atomicAdd(&g_cnt[clampi(d2.y)], 1);
        }
        return;
    }

    __nv_bfloat16* As = (__nv_bfloat16*)smbuf;            // [128][72]
    __nv_bfloat16* Bs = (__nv_bfloat16*)(smbuf + 18432);  // [128][72]
    unsigned short* Cs = (unsigned short*)smbuf;          // overlay
    int n0 = (blockIdx.x >> 1) * 128, c0 = (blockIdx.x & 1) * 128;
    int wm = wid >> 2, wn = wid & 3;
    uint32_t asb = (uint32_t)__cvta_generic_to_shared(As);
    uint32_t bsb = (uint32_t)__cvta_generic_to_shared(Bs);

    if (tid < 128) biasS[tid] = Wb[c0 + tid];

    float acc[4][4][4];
#pragma unroll
    for (int mt = 0; mt < 4; mt++)
#pragma unroll
        for (int nt = 0; nt < 4; nt++)
#pragma unroll
            for (int r = 0; r < 4; r++) acc[mt][nt][r] = 0.f;

    for (int kc = 0; kc < DXX; kc += 64) {
        __syncthreads();
#pragma unroll
        for (int j = 0; j < 8; j++) {
            int lin = tid + 256 * j;
            int row = lin >> 4, q = lin & 15;
            int gn = n0 + row; if (gn >= NN) gn = NN - 1;
            float4 v = *(const float4*)&x[(size_t)gn * DXX + kc + q * 4];
            uint2 o = make_uint2(pack_bf2(v.x, v.y), pack_bf2(v.z, v.w));
            *(uint2*)&As[row * 72 + q * 4] = o;
        }
#pragma unroll
        for (int j = 0; j < 8; j++) {
            int lin = tid + 256 * j;
            int row = lin >> 4, q = lin & 15;
            float4 v = *(const float4*)&Ww[(size_t)(c0 + row) * DXX + kc + q * 4];
            uint2 o = make_uint2(pack_bf2(v.x, v.y), pack_bf2(v.z, v.w));
            *(uint2*)&Bs[row * 72 + q * 4] = o;
        }
        __syncthreads();
#pragma unroll
        for (int ks = 0; ks < 4; ks++) {
            int k0 = ks * 16;
            uint32_t a[4][4], b[4][2];
#pragma unroll
            for (int mt = 0; mt < 4; mt++) {
                uint32_t ad = asb + ((wm * 64 + mt * 16 + (lane & 15)) * 72 +
                                     k0 + (lane >> 4) * 8) * 2;
                LDSM4(a[mt][0], a[mt][1], a[mt][2], a[mt][3], ad);
            }
#pragma unroll
            for (int nt = 0; nt < 4; nt++) {
                uint32_t bd = bsb + ((wn * 32 + nt * 8 + (lane & 7)) * 72 +
                                     k0 + ((lane >> 3) & 1) * 8) * 2;
                LDSM2(b[nt][0], b[nt][1], bd);
            }
#pragma unroll
            for (int mt = 0; mt < 4; mt++)
#pragma unroll
                for (int nt = 0; nt < 4; nt++)
                    MMA16816(acc[mt][nt], a[mt], b[nt]);
        }
    }
    __syncthreads();

    // epilogue: bias + fp8 pack into smem
    int tm = lane >> 2, tp = lane & 3;
#pragma unroll
    for (int mt = 0; mt < 4; mt++)
#pragma unroll
        for (int nt = 0; nt < 4; nt++) {
            int row = wm * 64 + mt * 16 + tm;
            int colp = wn * 16 + nt * 4 + tp;
            int c = colp * 2;
            unsigned short u0, u1;
            PACKF8(u0, acc[mt][nt][0] + biasS[c], acc[mt][nt][1] + biasS[c + 1]);
            PACKF8(u1, acc[mt][nt][2] + biasS[c], acc[mt][nt][3] + biasS[c + 1]);
            Cs[row * 72 + colp] = u0;
            Cs[(row + 8) * 72 + colp] = u1;
        }
    __syncthreads();
    // coalesced fp8 stores
#pragma unroll
    for (int j = 0; j < 4; j++) {
        int lin = tid + 256 * j;
        int row = lin >> 3, q = lin & 7;
        int gn = n0 + row;
        if (gn < NN) {
            uint4 v = *(uint4*)&Cs[row * 72 + q * 8];
            ((uint4*)g_Wxf8)[(size_t)gn * 16 + (c0 >> 4) + q] = v;
        }
    }

    // fused scores: this block holds 2 complete heads (cols c0..c0+127).
    {
        int row = tid & 127, hh = tid >> 7;
        int head = (c0 >> 6) + hh;
        int gn = n0 + row;
        if (gn < NN) {
            const unsigned short* cr = &Cs[row * 72 + hh * 32];
            const float* ai = aw + head * 128;
            const float* aj = ai + 64;
            float va = 0.f, vb = 0.f;
#pragma unroll
            for (int q = 0; q < 32; q++) {
                unsigned r; UNPF8(r, cr[q]);
                float2 f = __half22float2(*(__half2*)&r);
                va += f.x * ai[2 * q] + f.y * ai[2 * q + 1];
                vb += f.x * aj[2 * q] + f.y * aj[2 * q + 1];
            }
            g_sif[gn * 4 + head] = (va + ab[head]) * LOG2E;
            g_sjf[gn * 4 + head] = vb * LOG2E;
        }
    }
}

// ---------------- F2: fused scan (decoupled lookback) + scatter -------------
__global__ __launch_bounds__(256) void k_f2(const int* __restrict__ ei) {
    int tid = threadIdx.x;
    if (blockIdx.x < F2_SCAN) {
        // ---- scan role: 1024 elements per block, 4 per thread ----
        __shared__ int wsum[8];
        __shared__ int s_part[2];
        int b = blockIdx.x;
        int lane = tid & 31, wid = tid >> 5;
        int base = b * 1024 + tid * 4;
        if (b == 0) g_colsum[tid] = 0.f;            // reset for this run

        int v0 = 1, v1 = 1, v2 = 1, v3 = 1;          // +1 self-loop each
        if (base < NN) {
            int4 vv = *(int4*)&g_cnt[base];
            *(int4*)&g_cnt[base] = make_int4(0, 0, 0, 0);
            v0 += vv.x; v1 += vv.y; v2 += vv.z; v3 += vv.w;
        } else { v0 = v1 = v2 = v3 = 0; }
        int t = v0 + v1 + v2 + v3;

        int sc = t;
#pragma unroll
        for (int o = 1; o < 32; o <<= 1) {
            int u = __shfl_up_sync(0xffffffffu, sc, o);
            if (lane >= o) sc += u;
        }
        if (lane == 31) wsum[wid] = sc;
        __syncthreads();
        if (wid == 0 && lane < 8) {
            int ws = wsum[lane];
#pragma unroll
            for (int o = 1; o < 8; o <<= 1) {
                int u = __shfl_up_sync(0xffu, ws, o);
                if (lane >= o) ws += u;
            }
            wsum[lane] = ws;
        }
        __syncthreads();
        int incl = sc + (wid > 0 ? wsum[wid - 1] : 0);
        // publish block aggregate (single packed word)
        if (tid == 255) {
            unsigned pk = 0x80000000u | (unsigned)incl;
            asm volatile("st.release.gpu.u32 [%0], %1;" :: "l"(&g_bstat[b]), "r"(pk));
        }
        // parallel lookback: sum predecessor aggregates
        int val = 0;
        if (tid < b) {
            volatile unsigned* bs = g_bstat;
            unsigned w;
            do { w = bs[tid]; } while (!(w & 0x80000000u));
            val = (int)(w & 0x7fffffffu);
        }
        if (tid < 64) {
#pragma unroll
            for (int o = 16; o; o >>= 1) val += __shfl_xor_sync(0xffffffffu, val, o);
            if ((tid & 31) == 0) s_part[tid >> 5] = val;
        }
        __syncthreads();
        int offset = s_part[0] + s_part[1];
        if (base < NN) {
            int pre = offset + incl - t;
            int a1 = pre + v0, a2 = a1 + v1, a3 = a2 + v2, a4 = a3 + v3;
            g_rowptr[base + 1] = a1;
            g_rowptr[base + 2] = a2;
            g_rowptr[base + 3] = a3;
            g_rowptr[base + 4] = a4;
            *(int4*)&g_cur[base] = make_int4(pre, a1, a2, a3);
        }
        if (b == 0 && tid == 0) g_rowptr[0] = 0;
        __syncthreads();
        __threadfence();
        if (tid == 0) atomicAdd(&g_done, 1);
        return;
    }
    // ---- scatter role: wait for scan completion, then scatter ----
    if (tid == 0) {
        while (ld_acq(&g_done) < F2_SCAN) __nanosleep(128);
    }
    __syncthreads();
    int i = (blockIdx.x - F2_SCAN) * 256 + tid;
    if (i < EE / 2) {
        int2 s2 = *(const int2*)&ei[2 * i];
        int2 d2 = *(const int2*)&ei[EE + 2 * i];
        int pa = atomicAdd(&g_cur[clampi(d2.x)], 1);
        int pb = atomicAdd(&g_cur[clampi(d2.y)], 1);
        if (pa < ETOT) g_csr[pa] = clampi(s2.x);
        if (pb < ETOT) g_csr[pb] = clampi(s2.y);
    } else {
        int n = i - EE / 2;
        if (n < NN) {
            int pos = atomicAdd(&g_cur[n], 1);
            if (pos < ETOT) g_csr[pos] = n;
        }
    }
}

// ---------------- K6: edge softmax + fp8 gather, depth-2 pipe (R9) ---------
__global__ __launch_bounds__(256) void k_agg() {
    // reset lookback state for the next replay (f2 of this replay is done)
    if (blockIdx.x == 0) {
        if (threadIdx.x < F2_SCAN) g_bstat[threadIdx.x] = 0u;
        if (threadIdx.x == 63) g_done = 0;
    }
    int n = (blockIdx.x << 3) + (threadIdx.x >> 5);
    int lane = threadIdx.x & 31;
    if (n >= NN) return;
    int h = lane >> 3;
    int s = g_rowptr[n], en = g_rowptr[n + 1];
    float si = g_sif[n * 4 + h];

    __half2 acc0 = __float2half2_rn(0.f), acc1 = acc0, acc2 = acc0, acc3 = acc0;
    float den = 0.f;

    int srcA = g_csr[s];
    int srcB = (s + 1 < en) ? g_csr[s + 1] : srcA;
    float sjA = g_sjf[srcA * 4 + h], sjB = g_sjf[srcB * 4 + h];
    uint2 uA = g_Wxf8[(size_t)srcA * 32 + lane];
    uint2 uB = g_Wxf8[(size_t)srcB * 32 + lane];

    for (int e = s; e < en; e += 2) {
        int nA = (e + 2 < en) ? g_csr[e + 2] : srcA;
        int nB = (e + 3 < en) ? g_csr[e + 3] : srcA;
        float sjAn = g_sjf[nA * 4 + h];
        uint2 uAn = g_Wxf8[(size_t)nA * 32 + lane];
        float sjBn = g_sjf[nB * 4 + h];
        uint2 uBn = g_Wxf8[(size_t)nB * 32 + lane];

        {
            float t = si + sjA;
            t = fmaxf(t, NEG * t);
            float c; EX2A(c, t);
            den += c;
            __half2 ch = __float2half2_rn(c);
            __half2 w0, w1, w2, w3;
            f8_to_f16x2(uA.x, w0, w1);
            f8_to_f16x2(uA.y, w2, w3);
            acc0 = __hfma2(ch, w0, acc0);
            acc1 = __hfma2(ch, w1, acc1);
            acc2 = __hfma2(ch, w2, acc2);
            acc3 = __hfma2(ch, w3, acc3);
        }
        if (e + 1 < en) {
            float t = si + sjB;
            t = fmaxf(t, NEG * t);
            float c; EX2A(c, t);
            den += c;
            __half2 ch = __float2half2_rn(c);
            __half2 w0, w1, w2, w3;
            f8_to_f16x2(uB.x, w0, w1);
            f8_to_f16x2(uB.y, w2, w3);
            acc0 = __hfma2(ch, w0, acc0);
            acc1 = __hfma2(ch, w1, acc1);
            acc2 = __hfma2(ch, w2, acc2);
            acc3 = __hfma2(ch, w3, acc3);
        }
        sjA = sjAn; uA = uAn; sjB = sjBn; uB = uBn;
    }
    float inv = 1.f / den;
    float2 f0 = __half22float2(acc0);
    float2 f1 = __half22float2(acc1);
    float2 f2 = __half22float2(acc2);
    float2 f3 = __half22float2(acc3);
    unsigned p0, p1, p2, p3;
    PACKBF(p0, __expf(f0.x * inv), __expf(f0.y * inv));
    PACKBF(p1, __expf(f1.x * inv), __expf(f1.y * inv));
    PACKBF(p2, __expf(f2.x * inv), __expf(f2.y * inv));
    PACKBF(p3, __expf(f3.x * inv), __expf(f3.y * inv));
    g_aggh4[(size_t)n * 32 + lane] = make_uint4(p0, p1, p2, p3);
}

// ---------------- K7: column sum of E (250 blocks x 200 rows, 2 streams) ---
__global__ __launch_bounds__(256) void k_colsum() {
    const unsigned* Ah = (const unsigned*)g_aggh4;
    int tid = threadIdx.x;
    int c2 = tid & 127;                // uint index = column pair
    int g = tid >> 7;
    int n0 = blockIdx.x * 200;
    float a0 = 0.f, a1 = 0.f, b0 = 0.f, b1 = 0.f;
    for (int r = g; r < 200; r += 4) {
        unsigned u = Ah[(size_t)(n0 + r) * 128 + c2];
        unsigned w = Ah[(size_t)(n0 + r + 2) * 128 + c2];
        a0 += bflo(u); a1 += bfhi(u);
        b0 += bflo(w); b1 += bfhi(w);
    }
    atomicAdd(&g_colsum[c2 * 2], a0 + b0);
    atomicAdd(&g_colsum[c2 * 2 + 1], a1 + b1);
}

// ---------------- K8: out = (E*siv) @ Wo^T + b  (bf16 mma.sync) ------------
__global__ __launch_bounds__(256) void k_out(const float* __restrict__ Wo,
                                             const float* __restrict__ Wob,
                                             float* __restrict__ out) {
    __shared__ __align__(16) char smbuf[34816];
    __shared__ float sivS[CC];
    __nv_bfloat16* As = (__nv_bfloat16*)smbuf;            // [128][72]
    __nv_bfloat16* Bs = (__nv_bfloat16*)(smbuf + 18432);  // [64][72]
    float* Csf = (float*)smbuf;                           // overlay
    int tid = threadIdx.x, lane = tid & 31, wid = tid >> 5;
    int n0 = blockIdx.x * 128;
    int wm = wid & 3, wn = wid >> 2;
    uint32_t asb = (uint32_t)__cvta_generic_to_shared(As);
    uint32_t bsb = (uint32_t)__cvta_generic_to_shared(Bs);

    sivS[tid] = 1.f / g_colsum[tid];

    float acc[2][4][4];
#pragma unroll
    for (int mt = 0; mt < 2; mt++)
#pragma unroll
        for (int nt = 0; nt < 4; nt++)
#pragma unroll
            for (int r = 0; r < 4; r++) acc[mt][nt][r] = 0.f;

    for (int cb = 0; cb < CC; cb += 64) {
        __syncthreads();
#pragma unroll
        for (int j = 0; j < 4; j++) {
            int lin = tid + 256 * j;
            int row = lin >> 3, q = lin & 7;
            int gn = n0 + row; if (gn >= NN) gn = NN - 1;
            uint4 u = g_aggh4[(size_t)gn * 32 + (cb >> 3) + q];
            unsigned ua[4] = {u.x, u.y, u.z, u.w};
            unsigned ou[4];
#pragma unroll
            for (int i = 0; i < 4; i++) {
                int c = cb + q * 8 + 2 * i;
                ou[i] = pack_bf2(bflo(ua[i]) * sivS[c], bfhi(ua[i]) * sivS[c + 1]);
            }
            *(uint4*)&As[row * 72 + q * 8] = make_uint4(ou[0], ou[1], ou[2], ou[3]);
        }
#pragma unroll
        for (int j = 0; j < 4; j++) {
            int lin = tid + 256 * j;
            int row = lin >> 4, q = lin & 15;
            float4 v = *(const float4*)&Wo[(size_t)row * CC + cb + q * 4];
            uint2 o = make_uint2(pack_bf2(v.x, v.y), pack_bf2(v.z, v.w));
            *(uint2*)&Bs[row * 72 + q * 4] = o;
        }
        __syncthreads();
#pragma unroll
        for (int ks = 0; ks < 4; ks++) {
            int k0 = ks * 16;
            uint32_t a[2][4], b[4][2];
#pragma unroll
            for (int mt = 0; mt < 2; mt++) {
                uint32_t ad = asb + ((wm * 32 + mt * 16 + (lane & 15)) * 72 +
                                     k0 + (lane >> 4) * 8) * 2;
                LDSM4(a[mt][0], a[mt][1], a[mt][2], a[mt][3], ad);
            }
#pragma unroll
            for (int nt = 0; nt < 4; nt++) {
                uint32_t bd = bsb + ((wn * 32 + nt * 8 + (lane & 7)) * 72 +
                                     k0 + ((lane >> 3) & 1) * 8) * 2;
                LDSM2(b[nt][0], b[nt][1], bd);
            }
#pragma unroll
            for (int mt = 0; mt < 2; mt++)
#pragma unroll
                for (int nt = 0; nt < 4; nt++)
                    MMA16816(acc[mt][nt], a[mt], b[nt]);
        }
    }
    __syncthreads();

    int tm = lane >> 2, tp = lane & 3;
#pragma unroll
    for (int mt = 0; mt < 2; mt++)
#pragma unroll
        for (int nt = 0; nt < 4; nt++) {
            int row = wm * 32 + mt * 16 + tm;
            int col = wn * 32 + nt * 8 + 2 * tp;
            Csf[row * 68 + col] = acc[mt][nt][0];
            Csf[row * 68 + col + 1] = acc[mt][nt][1];
            Csf[(row + 8) * 68 + col] = acc[mt][nt][2];
            Csf[(row + 8) * 68 + col + 1] = acc[mt][nt][3];
        }
    __syncthreads();
#pragma unroll
    for (int j = 0; j < 8; j++) {
        int lin = tid + 256 * j;
        int row = lin >> 4, q = lin & 15;
        int gn = n0 + row;
        if (gn < NN) {
            float4 v = *(float4*)&Csf[row * 68 + q * 4];
            float4 b = *(const float4*)&Wob[q * 4];
            float4 o = {v.x + b.x, v.y + b.y, v.z + b.z, v.w + b.w};
            *(float4*)&out[(size_t)gn * 64 + q * 4] = o;
        }
    }
}

// ---------------- launch ----------------------------------------------------
extern "C" void kernel_launch(void* const* d_in, const int* in_sizes, int n_in,
                              void* d_out, int out_size) {
    (void)out_size;
    const void* p[8];
    for (int j = 0; j < 8; j++) p[j] = (j < n_in) ? d_in[j] : 0;
    const int want[8] = {2 * EE, NN * DXX, KH * DHH * DXX, KH * DHH,
                         KH * 2 * DHH, KH, DHH * CC, DHH};
    for (int j = 0; j < 8; j++)
        for (int i = 0; i < n_in; i++)
            if (in_sizes[i] == want[j]) { p[j] = d_in[i]; break; }

    const int*   ei  = (const int*)p[0];
    const float* x   = (const float*)p[1];
    const float* Ww  = (const float*)p[2];
    const float* Wb  = (const float*)p[3];
    const float* aw  = (const float*)p[4];
    const float* ab  = (const float*)p[5];
    const float* Wo  = (const float*)p[6];
    const float* Wob = (const float*)p[7];
    float* out = (float*)d_out;

    k_f1<<<F1_WX + F1_HIST, 256>>>(x, Ww, Wb, aw, ab, ei);
    k_f2<<<F2_SCAN + F2_SCAT, 256>>>(ei);
    k_agg<<<(NN + 7) / 8, 256>>>();
    k_colsum<<<250, 256>>>();
    k_out<<<391, 256>>>(Wo, Wob, out);
}

// round 16
// speedup vs baseline: 1.3630x; 1.0294x over previous
#include <cuda_runtime.h>
#include <cuda_bf16.h>
#include <cuda_fp16.h>
#include <cstdint>

typedef unsigned long long ull;

#define NN 50000
#define EE 1600000
#define ETOT 1650000
#define KH 4
#define DHH 64
#define DXX 128
#define CC 256          // KH*DHH
#define NEG 0.01f
#define LOG2E 1.44269504f

// f1: blocks [0,782) = wx tiles (+ fused scores), then hist (2 edges/thread)
#define F1_WX 782
#define F1_HIST 3125
// f2: 49 scan blocks (1024 elems each, 4/thread) + scatter blocks
#define F2_SCAN 49
#define F2_SCAT 3321

// ---------------- scratch (static device globals; zero-init at load) --------
__device__ uint2 g_Wxf8[NN * 32];        // 12.8 MB  fp8 Wx[n][c] (256B/row)
__device__ uint4 g_aggh4[NN * 32];       // 25.6 MB  bf16 E = exp(agg)
__device__ float g_sif[NN * KH];         // (si + ab) * log2e, per head
__device__ float g_sjf[NN * KH];         // sj * log2e, per head
__device__ int g_cnt[NN];                // zero-init; re-zeroed by f2 scan
__device__ int g_rowptr[NN + 1];
__device__ int g_cur[NN];
__device__ unsigned g_bstat[64];         // packed READY|total; reset by k_agg
__device__ int g_done;                   // reset by k_agg
__device__ int g_csr[ETOT];              // src indices grouped by dst
__device__ float g_colsum[CC];           // zeroed by f2 scan block 0

// ---------------- helpers ---------------------------------------------------
__device__ __forceinline__ float bflo(unsigned u) { return __uint_as_float(u << 16); }
__device__ __forceinline__ float bfhi(unsigned u) { return __uint_as_float(u & 0xffff0000u); }
__device__ __forceinline__ int clampi(int v) {
    return v < 0 ? 0 : (v >= NN ? NN - 1 : v);
}
__device__ __forceinline__ int ld_acq(const int* p) {
    int v;
    asm volatile("ld.acquire.gpu.s32 %0, [%1];" : "=r"(v) : "l"(p));
    return v;
}

#define PACKBF(r, lo, hi) asm("cvt.rn.bf16x2.f32 %0, %1, %2;" : "=r"(r) : "f"(hi), "f"(lo))
#define PACKF8(r, lo, hi) \
    asm("cvt.rn.satfinite.e4m3x2.f32 %0, %1, %2;" : "=h"(r) : "f"(hi), "f"(lo))
#define UNPF8(d, s) asm("cvt.rn.f16x2.e4m3x2 %0, %1;" : "=r"(d) : "h"(s))
#define EX2A(d, s) asm("ex2.approx.ftz.f32 %0, %1;" : "=f"(d) : "f"(s))

__device__ __forceinline__ void f8_to_f16x2(unsigned u32v, __half2& lo, __half2& hi) {
    unsigned short sl = (unsigned short)(u32v & 0xffffu);
    unsigned short sh = (unsigned short)(u32v >> 16);
    unsigned a, b;
    UNPF8(a, sl);
    UNPF8(b, sh);
    lo = *(__half2*)&a;
    hi = *(__half2*)&b;
}

#define LDSM4(r0, r1, r2, r3, a) asm volatile( \
    "ldmatrix.sync.aligned.m8n8.x4.shared.b16 {%0,%1,%2,%3}, [%4];" \
    : "=r"(r0), "=r"(r1), "=r"(r2), "=r"(r3) : "r"(a))
#define LDSM2(r0, r1, a) asm volatile( \
    "ldmatrix.sync.aligned.m8n8.x2.shared.b16 {%0,%1}, [%2];" \
    : "=r"(r0), "=r"(r1) : "r"(a))
#define MMA16816(d, a, b) asm volatile( \
    "mma.sync.aligned.m16n8k16.row.col.f32.bf16.bf16.f32 " \
    "{%0,%1,%2,%3}, {%4,%5,%6,%7}, {%8,%9}, {%0,%1,%2,%3};" \
    : "+f"((d)[0]), "+f"((d)[1]), "+f"((d)[2]), "+f"((d)[3]) \
    : "r"((a)[0]), "r"((a)[1]), "r"((a)[2]), "r"((a)[3]), "r"((b)[0]), "r"((b)[1]))

__device__ __forceinline__ unsigned pack_bf2(float lo, float hi) {
    unsigned r; PACKBF(r, lo, hi); return r;
}

// ---------------- F1: Wx GEMM + fused scores ∥ degree hist ------------------
__global__ __launch_bounds__(256) void k_f1(const float* __restrict__ x,
                                            const float* __restrict__ Ww,
                                            const float* __restrict__ Wb,
                                            const float* __restrict__ aw,
                                            const float* __restrict__ ab,
                                            const int* __restrict__ ei) {
    __shared__ __align__(16) char smbuf[36864];
    __shared__ float biasS[128];
    int tid = threadIdx.x, lane = tid & 31, wid = tid >> 5;

    if (blockIdx.x >= F1_WX) {
        // ---- hist role: 2 edges/thread ----
        int i = (blockIdx.x - F1_WX) * 256 + tid;
        if (i < EE / 2) {
            int2 d2 = *(const int2*)&ei[EE + 2 * i];
            atomicAdd(&g_cnt[clampi(d2.x)], 1);
            atomicAdd(&g_cnt[clampi(d2.y)], 1);
        }
        return;
    }

    __nv_bfloat16* As = (__nv_bfloat16*)smbuf;            // [128][72]
    __nv_bfloat16* Bs = (__nv_bfloat16*)(smbuf + 18432);  // [128][72]
    unsigned short* Cs = (unsigned short*)smbuf;          // overlay
    int n0 = (blockIdx.x >> 1) * 128, c0 = (blockIdx.x & 1) * 128;
    int wm = wid >> 2, wn = wid & 3;
    uint32_t asb = (uint32_t)__cvta_generic_to_shared(As);
    uint32_t bsb = (uint32_t)__cvta_generic_to_shared(Bs);

    if (tid < 128) biasS[tid] = Wb[c0 + tid];

    float acc[4][4][4];
#pragma unroll
    for (int mt = 0; mt < 4; mt++)
#pragma unroll
        for (int nt = 0; nt < 4; nt++)
#pragma unroll
            for (int r = 0; r < 4; r++) acc[mt][nt][r] = 0.f;

    for (int kc = 0; kc < DXX; kc += 64) {
        __syncthreads();
#pragma unroll
        for (int j = 0; j < 8; j++) {
            int lin = tid + 256 * j;
            int row = lin >> 4, q = lin & 15;
            int gn = n0 + row; if (gn >= NN) gn = NN - 1;
            float4 v = *(const float4*)&x[(size_t)gn * DXX + kc + q * 4];
            uint2 o = make_uint2(pack_bf2(v.x, v.y), pack_bf2(v.z, v.w));
            *(uint2*)&As[row * 72 + q * 4] = o;
        }
#pragma unroll
        for (int j = 0; j < 8; j++) {
            int lin = tid + 256 * j;
            int row = lin >> 4, q = lin & 15;
            float4 v = *(const float4*)&Ww[(size_t)(c0 + row) * DXX + kc + q * 4];
            uint2 o = make_uint2(pack_bf2(v.x, v.y), pack_bf2(v.z, v.w));
            *(uint2*)&Bs[row * 72 + q * 4] = o;
        }
        __syncthreads();
#pragma unroll
        for (int ks = 0; ks < 4; ks++) {
            int k0 = ks * 16;
            uint32_t a[4][4], b[4][2];
#pragma unroll
            for (int mt = 0; mt < 4; mt++) {
                uint32_t ad = asb + ((wm * 64 + mt * 16 + (lane & 15)) * 72 +
                                     k0 + (lane >> 4) * 8) * 2;
                LDSM4(a[mt][0], a[mt][1], a[mt][2], a[mt][3], ad);
            }
#pragma unroll
            for (int nt = 0; nt < 4; nt++) {
                uint32_t bd = bsb + ((wn * 32 + nt * 8 + (lane & 7)) * 72 +
                                     k0 + ((lane >> 3) & 1) * 8) * 2;
                LDSM2(b[nt][0], b[nt][1], bd);
            }
#pragma unroll
            for (int mt = 0; mt < 4; mt++)
#pragma unroll
                for (int nt = 0; nt < 4; nt++)
                    MMA16816(acc[mt][nt], a[mt], b[nt]);
        }
    }
    __syncthreads();

    // epilogue: bias + fp8 pack into smem
    int tm = lane >> 2, tp = lane & 3;
#pragma unroll
    for (int mt = 0; mt < 4; mt++)
#pragma unroll
        for (int nt = 0; nt < 4; nt++) {
            int row = wm * 64 + mt * 16 + tm;
            int colp = wn * 16 + nt * 4 + tp;
            int c = colp * 2;
            unsigned short u0, u1;
            PACKF8(u0, acc[mt][nt][0] + biasS[c], acc[mt][nt][1] + biasS[c + 1]);
            PACKF8(u1, acc[mt][nt][2] + biasS[c], acc[mt][nt][3] + biasS[c + 1]);
            Cs[row * 72 + colp] = u0;
            Cs[(row + 8) * 72 + colp] = u1;
        }
    __syncthreads();
    // coalesced fp8 stores
#pragma unroll
    for (int j = 0; j < 4; j++) {
        int lin = tid + 256 * j;
        int row = lin >> 3, q = lin & 7;
        int gn = n0 + row;
        if (gn < NN) {
            uint4 v = *(uint4*)&Cs[row * 72 + q * 8];
            ((uint4*)g_Wxf8)[(size_t)gn * 16 + (c0 >> 4) + q] = v;
        }
    }

    // fused scores: this block holds 2 complete heads (cols c0..c0+127).
    {
        int row = tid & 127, hh = tid >> 7;
        int head = (c0 >> 6) + hh;
        int gn = n0 + row;
        if (gn < NN) {
            const unsigned short* cr = &Cs[row * 72 + hh * 32];
            const float* ai = aw + head * 128;
            const float* aj = ai + 64;
            float va = 0.f, vb = 0.f;
#pragma unroll
            for (int q = 0; q < 32; q++) {
                unsigned r; UNPF8(r, cr[q]);
                float2 f = __half22float2(*(__half2*)&r);
                va += f.x * ai[2 * q] + f.y * ai[2 * q + 1];
                vb += f.x * aj[2 * q] + f.y * aj[2 * q + 1];
            }
            g_sif[gn * 4 + head] = (va + ab[head]) * LOG2E;
            g_sjf[gn * 4 + head] = vb * LOG2E;
        }
    }
}

// ---------------- F2: fused scan (decoupled lookback) + scatter -------------
__global__ __launch_bounds__(256) void k_f2(const int* __restrict__ ei) {
    int tid = threadIdx.x;
    if (blockIdx.x < F2_SCAN) {
        // ---- scan role: 1024 elements per block, 4 per thread ----
        __shared__ int wsum[8];
        __shared__ int s_part[2];
        int b = blockIdx.x;
        int lane = tid & 31, wid = tid >> 5;
        int base = b * 1024 + tid * 4;
        if (b == 0) g_colsum[tid] = 0.f;            // reset for this run

        int v0 = 1, v1 = 1, v2 = 1, v3 = 1;          // +1 self-loop each
        if (base < NN) {
            int4 vv = *(int4*)&g_cnt[base];
            *(int4*)&g_cnt[base] = make_int4(0, 0, 0, 0);
            v0 += vv.x; v1 += vv.y; v2 += vv.z; v3 += vv.w;
        } else { v0 = v1 = v2 = v3 = 0; }
        int t = v0 + v1 + v2 + v3;

        int sc = t;
#pragma unroll
        for (int o = 1; o < 32; o <<= 1) {
            int u = __shfl_up_sync(0xffffffffu, sc, o);
            if (lane >= o) sc += u;
        }
        if (lane == 31) wsum[wid] = sc;
        __syncthreads();
        if (wid == 0 && lane < 8) {
            int ws = wsum[lane];
#pragma unroll
            for (int o = 1; o < 8; o <<= 1) {
                int u = __shfl_up_sync(0xffu, ws, o);
                if (lane >= o) ws += u;
            }
            wsum[lane] = ws;
        }
        __syncthreads();
        int incl = sc + (wid > 0 ? wsum[wid - 1] : 0);
        // publish block aggregate (single packed word)
        if (tid == 255) {
            unsigned pk = 0x80000000u | (unsigned)incl;
            asm volatile("st.release.gpu.u32 [%0], %1;" :: "l"(&g_bstat[b]), "r"(pk));
        }
        // parallel lookback: sum predecessor aggregates
        int val = 0;
        if (tid < b) {
            volatile unsigned* bs = g_bstat;
            unsigned w;
            do { w = bs[tid]; } while (!(w & 0x80000000u));
            val = (int)(w & 0x7fffffffu);
        }
        if (tid < 64) {
#pragma unroll
            for (int o = 16; o; o >>= 1) val += __shfl_xor_sync(0xffffffffu, val, o);
            if ((tid & 31) == 0) s_part[tid >> 5] = val;
        }
        __syncthreads();
        int offset = s_part[0] + s_part[1];
        if (base < NN) {
            int pre = offset + incl - t;
            int a1 = pre + v0, a2 = a1 + v1, a3 = a2 + v2, a4 = a3 + v3;
            g_rowptr[base + 1] = a1;
            g_rowptr[base + 2] = a2;
            g_rowptr[base + 3] = a3;
            g_rowptr[base + 4] = a4;
            *(int4*)&g_cur[base] = make_int4(pre, a1, a2, a3);
        }
        if (b == 0 && tid == 0) g_rowptr[0] = 0;
        __syncthreads();
        __threadfence();
        if (tid == 0) atomicAdd(&g_done, 1);
        return;
    }
    // ---- scatter role: wait for scan completion, then scatter ----
    if (tid == 0) {
        while (ld_acq(&g_done) < F2_SCAN) __nanosleep(128);
    }
    __syncthreads();
    int i = (blockIdx.x - F2_SCAN) * 256 + tid;
    if (i < EE / 2) {
        int2 s2 = *(const int2*)&ei[2 * i];
        int2 d2 = *(const int2*)&ei[EE + 2 * i];
        int pa = atomicAdd(&g_cur[clampi(d2.x)], 1);
        int pb = atomicAdd(&g_cur[clampi(d2.y)], 1);
        if (pa < ETOT) g_csr[pa] = clampi(s2.x);
        if (pb < ETOT) g_csr[pb] = clampi(s2.y);
    } else {
        int n = i - EE / 2;
        if (n < NN) {
            int pos = atomicAdd(&g_cur[n], 1);
            if (pos < ETOT) g_csr[pos] = n;
        }
    }
}

// ---------------- K6: edge softmax + fp8 gather, depth-2 pipe (R9) ---------
__global__ __launch_bounds__(256) void k_agg() {
    // reset lookback state for the next replay (f2 of this replay is done)
    if (blockIdx.x == 0) {
        if (threadIdx.x < F2_SCAN) g_bstat[threadIdx.x] = 0u;
        if (threadIdx.x == 63) g_done = 0;
    }
    int n = (blockIdx.x << 3) + (threadIdx.x >> 5);
    int lane = threadIdx.x & 31;
    if (n >= NN) return;
    int h = lane >> 3;
    int s = g_rowptr[n], en = g_rowptr[n + 1];
    float si = g_sif[n * 4 + h];

    __half2 acc0 = __float2half2_rn(0.f), acc1 = acc0, acc2 = acc0, acc3 = acc0;
    float den = 0.f;

    int srcA = g_csr[s];
    int srcB = (s + 1 < en) ? g_csr[s + 1] : srcA;
    float sjA = g_sjf[srcA * 4 + h], sjB = g_sjf[srcB * 4 + h];
    uint2 uA = g_Wxf8[(size_t)srcA * 32 + lane];
    uint2 uB = g_Wxf8[(size_t)srcB * 32 + lane];

    for (int e = s; e < en; e += 2) {
        int nA = (e + 2 < en) ? g_csr[e + 2] : srcA;
        int nB = (e + 3 < en) ? g_csr[e + 3] : srcA;
        float sjAn = g_sjf[nA * 4 + h];
        uint2 uAn = g_Wxf8[(size_t)nA * 32 + lane];
        float sjBn = g_sjf[nB * 4 + h];
        uint2 uBn = g_Wxf8[(size_t)nB * 32 + lane];

        {
            float t = si + sjA;
            t = fmaxf(t, NEG * t);
            float c; EX2A(c, t);
            den += c;
            __half2 ch = __float2half2_rn(c);
            __half2 w0, w1, w2, w3;
            f8_to_f16x2(uA.x, w0, w1);
            f8_to_f16x2(uA.y, w2, w3);
            acc0 = __hfma2(ch, w0, acc0);
            acc1 = __hfma2(ch, w1, acc1);
            acc2 = __hfma2(ch, w2, acc2);
            acc3 = __hfma2(ch, w3, acc3);
        }
        if (e + 1 < en) {
            float t = si + sjB;
            t = fmaxf(t, NEG * t);
            float c; EX2A(c, t);
            den += c;
            __half2 ch = __float2half2_rn(c);
            __half2 w0, w1, w2, w3;
            f8_to_f16x2(uB.x, w0, w1);
            f8_to_f16x2(uB.y, w2, w3);
            acc0 = __hfma2(ch, w0, acc0);
            acc1 = __hfma2(ch, w1, acc1);
            acc2 = __hfma2(ch, w2, acc2);
            acc3 = __hfma2(ch, w3, acc3);
        }
        sjA = sjAn; uA = uAn; sjB = sjBn; uB = uBn;
    }
    float inv = 1.f / den;
    float2 f0 = __half22float2(acc0);
    float2 f1 = __half22float2(acc1);
    float2 f2 = __half22float2(acc2);
    float2 f3 = __half22float2(acc3);
    unsigned p0, p1, p2, p3;
    PACKBF(p0, __expf(f0.x * inv), __expf(f0.y * inv));
    PACKBF(p1, __expf(f1.x * inv), __expf(f1.y * inv));
    PACKBF(p2, __expf(f2.x * inv), __expf(f2.y * inv));
    PACKBF(p3, __expf(f3.x * inv), __expf(f3.y * inv));
    g_aggh4[(size_t)n * 32 + lane] = make_uint4(p0, p1, p2, p3);
}

// ---------------- K7: column sum of E (block-reduced atomics, 4 streams) ---
__global__ __launch_bounds__(256) void k_colsum() {
    __shared__ float sh0[256];
    __shared__ float sh1[256];
    const unsigned* Ah = (const unsigned*)g_aggh4;
    int tid = threadIdx.x;
    int c2 = tid & 127;                // uint index = column pair
    int g = tid >> 7;                  // row-stream group (0/1)
    int n0 = blockIdx.x * 200;
    float a0 = 0.f, a1 = 0.f, b0 = 0.f, b1 = 0.f;
    for (int r = g; r < 200; r += 4) {
        unsigned u = Ah[(size_t)(n0 + r) * 128 + c2];
        unsigned w = Ah[(size_t)(n0 + r + 2) * 128 + c2];
        a0 += bflo(u); a1 += bfhi(u);
        b0 += bflo(w); b1 += bfhi(w);
    }
    sh0[tid] = a0 + b0;
    sh1[tid] = a1 + b1;
    __syncthreads();
    if (tid < 128) {
        atomicAdd(&g_colsum[c2 * 2], sh0[tid] + sh0[tid + 128]);
        atomicAdd(&g_colsum[c2 * 2 + 1], sh1[tid] + sh1[tid + 128]);
    }
}

// ---------------- K8: out = (E*siv) @ Wo^T + b  (bf16 mma.sync) ------------
__global__ __launch_bounds__(256) void k_out(const float* __restrict__ Wo,
                                             const float* __restrict__ Wob,
                                             float* __restrict__ out) {
    __shared__ __align__(16) char smbuf[34816];
    __shared__ float sivS[CC];
    __nv_bfloat16* As = (__nv_bfloat16*)smbuf;            // [128][72]
    __nv_bfloat16* Bs = (__nv_bfloat16*)(smbuf + 18432);  // [64][72]
    float* Csf = (float*)smbuf;                           // overlay
    int tid = threadIdx.x, lane = tid & 31, wid = tid >> 5;
    int n0 = blockIdx.x * 128;
    int wm = wid & 3, wn = wid >> 2;
    uint32_t asb = (uint32_t)__cvta_generic_to_shared(As);
    uint32_t bsb = (uint32_t)__cvta_generic_to_shared(Bs);

    sivS[tid] = 1.f / g_colsum[tid];

    float acc[2][4][4];
#pragma unroll
    for (int mt = 0; mt < 2; mt++)
#pragma unroll
        for (int nt = 0; nt < 4; nt++)
#pragma unroll
            for (int r = 0; r < 4; r++) acc[mt][nt][r] = 0.f;

    for (int cb = 0; cb < CC; cb += 64) {
        __syncthreads();
#pragma unroll
        for (int j = 0; j < 4; j++) {
            int lin = tid + 256 * j;
            int row = lin >> 3, q = lin & 7;
            int gn = n0 + row; if (gn >= NN) gn = NN - 1;
            uint4 u = g_aggh4[(size_t)gn * 32 + (cb >> 3) + q];
            unsigned ua[4] = {u.x, u.y, u.z, u.w};
            unsigned ou[4];
#pragma unroll
            for (int i = 0; i < 4; i++) {
                int c = cb + q * 8 + 2 * i;
                ou[i] = pack_bf2(bflo(ua[i]) * sivS[c], bfhi(ua[i]) * sivS[c + 1]);
            }
            *(uint4*)&As[row * 72 + q * 8] = make_uint4(ou[0], ou[1], ou[2], ou[3]);
        }
#pragma unroll
        for (int j = 0; j < 4; j++) {
            int lin = tid + 256 * j;
            int row = lin >> 4, q = lin & 15;
            float4 v = *(const float4*)&Wo[(size_t)row * CC + cb + q * 4];
            uint2 o = make_uint2(pack_bf2(v.x, v.y), pack_bf2(v.z, v.w));
            *(uint2*)&Bs[row * 72 + q * 4] = o;
        }
        __syncthreads();
#pragma unroll
        for (int ks = 0; ks < 4; ks++) {
            int k0 = ks * 16;
            uint32_t a[2][4], b[4][2];
#pragma unroll
            for (int mt = 0; mt < 2; mt++) {
                uint32_t ad = asb + ((wm * 32 + mt * 16 + (lane & 15)) * 72 +
                                     k0 + (lane >> 4) * 8) * 2;
                LDSM4(a[mt][0], a[mt][1], a[mt][2], a[mt][3], ad);
            }
#pragma unroll
            for (int nt = 0; nt < 4; nt++) {
                uint32_t bd = bsb + ((wn * 32 + nt * 8 + (lane & 7)) * 72 +
                                     k0 + ((lane >> 3) & 1) * 8) * 2;
                LDSM2(b[nt][0], b[nt][1], bd);
            }
#pragma unroll
            for (int mt = 0; mt < 2; mt++)
#pragma unroll
                for (int nt = 0; nt < 4; nt++)
                    MMA16816(acc[mt][nt], a[mt], b[nt]);
        }
    }
    __syncthreads();

    int tm = lane >> 2, tp = lane & 3;
#pragma unroll
    for (int mt = 0; mt < 2; mt++)
#pragma unroll
        for (int nt = 0; nt < 4; nt++) {
            int row = wm * 32 + mt * 16 + tm;
            int col = wn * 32 + nt * 8 + 2 * tp;
            Csf[row * 68 + col] = acc[mt][nt][0];
            Csf[row * 68 + col + 1] = acc[mt][nt][1];
            Csf[(row + 8) * 68 + col] = acc[mt][nt][2];
            Csf[(row + 8) * 68 + col + 1] = acc[mt][nt][3];
        }
    __syncthreads();
#pragma unroll
    for (int j = 0; j < 8; j++) {
        int lin = tid + 256 * j;
        int row = lin >> 4, q = lin & 15;
        int gn = n0 + row;
        if (gn < NN) {
            float4 v = *(float4*)&Csf[row * 68 + q * 4];
            float4 b = *(const float4*)&Wob[q * 4];
            float4 o = {v.x + b.x, v.y + b.y, v.z + b.z, v.w + b.w};
            *(float4*)&out[(size_t)gn * 64 + q * 4] = o;
        }
    }
}

// ---------------- launch ----------------------------------------------------
extern "C" void kernel_launch(void* const* d_in, const int* in_sizes, int n_in,
                              void* d_out, int out_size) {
    (void)out_size;
    const void* p[8];
    for (int j = 0; j < 8; j++) p[j] = (j < n_in) ? d_in[j] : 0;
    const int want[8] = {2 * EE, NN * DXX, KH * DHH * DXX, KH * DHH,
                         KH * 2 * DHH, KH, DHH * CC, DHH};
    for (int j = 0; j < 8; j++)
        for (int i = 0; i < n_in; i++)
            if (in_sizes[i] == want[j]) { p[j] = d_in[i]; break; }

    const int*   ei  = (const int*)p[0];
    const float* x   = (const float*)p[1];
    const float* Ww  = (const float*)p[2];
    const float* Wb  = (const float*)p[3];
    const float* aw  = (const float*)p[4];
    const float* ab  = (const float*)p[5];
    const float* Wo  = (const float*)p[6];
    const float* Wob = (const float*)p[7];
    float* out = (float*)d_out;

    k_f1<<<F1_WX + F1_HIST, 256>>>(x, Ww, Wb, aw, ab, ei);
    k_f2<<<F2_SCAN + F2_SCAT, 256>>>(ei);
    k_agg<<<(NN + 7) / 8, 256>>>();
    k_colsum<<<250, 256>>>();
    k_out<<<391, 256>>>(Wo, Wob, out);
}

// round 17
// speedup vs baseline: 1.4387x; 1.0555x over previous
#include <cuda_runtime.h>
#include <cuda_bf16.h>
#include <cuda_fp16.h>
#include <cstdint>

typedef unsigned long long ull;

#define NN 50000
#define EE 1600000
#define ETOT 1650000
#define KH 4
#define DHH 64
#define DXX 128
#define CC 256          // KH*DHH
#define NEG 0.01f
#define LOG2E 1.44269504f

// f1: blocks [0,782) = wx tiles (+ fused scores), then hist (2 edges/thread)
#define F1_WX 782
#define F1_HIST 3125
// f2: 49 scan blocks (1024 elems each, 4/thread) + scatter blocks
#define F2_SCAN 49
#define F2_SCAT 3321

// ---------------- scratch (static device globals; zero-init at load) --------
__device__ uint2 g_Wxf8[NN * 32];        // 12.8 MB  fp8 Wx[n][c] (256B/row)
__device__ uint4 g_aggh4[NN * 32];       // 25.6 MB  bf16 E = exp(agg)
__device__ float g_sif[NN * KH];         // (si + ab) * log2e, per head
__device__ float g_sjf[NN * KH];         // sj * log2e, per head
__device__ int g_cnt[NN];                // zero-init; re-zeroed by f2 scan
__device__ int g_rowptr[NN + 1];
__device__ int g_cur[NN];
__device__ unsigned g_bstat[64];         // packed READY|total; reset by k_agg
__device__ int g_done;                   // reset by k_agg
__device__ int g_csr[ETOT];              // src indices grouped by dst
__device__ float g_colsum[CC];           // zeroed by f2 scan block 0

// ---------------- helpers ---------------------------------------------------
__device__ __forceinline__ float bflo(unsigned u) { return __uint_as_float(u << 16); }
__device__ __forceinline__ float bfhi(unsigned u) { return __uint_as_float(u & 0xffff0000u); }
__device__ __forceinline__ int clampi(int v) {
    return v < 0 ? 0 : (v >= NN ? NN - 1 : v);
}
__device__ __forceinline__ int ld_acq(const int* p) {
    int v;
    asm volatile("ld.acquire.gpu.s32 %0, [%1];" : "=r"(v) : "l"(p));
    return v;
}

#define PACKBF(r, lo, hi) asm("cvt.rn.bf16x2.f32 %0, %1, %2;" : "=r"(r) : "f"(hi), "f"(lo))
#define PACKF8(r, lo, hi) \
    asm("cvt.rn.satfinite.e4m3x2.f32 %0, %1, %2;" : "=h"(r) : "f"(hi), "f"(lo))
#define UNPF8(d, s) asm("cvt.rn.f16x2.e4m3x2 %0, %1;" : "=r"(d) : "h"(s))
#define EX2A(d, s) asm("ex2.approx.ftz.f32 %0, %1;" : "=f"(d) : "f"(s))

__device__ __forceinline__ void f8_to_f16x2(unsigned u32v, __half2& lo, __half2& hi) {
    unsigned short sl = (unsigned short)(u32v & 0xffffu);
    unsigned short sh = (unsigned short)(u32v >> 16);
    unsigned a, b;
    UNPF8(a, sl);
    UNPF8(b, sh);
    lo = *(__half2*)&a;
    hi = *(__half2*)&b;
}

#define LDSM4(r0, r1, r2, r3, a) asm volatile( \
    "ldmatrix.sync.aligned.m8n8.x4.shared.b16 {%0,%1,%2,%3}, [%4];" \
    : "=r"(r0), "=r"(r1), "=r"(r2), "=r"(r3) : "r"(a))
#define LDSM2(r0, r1, a) asm volatile( \
    "ldmatrix.sync.aligned.m8n8.x2.shared.b16 {%0,%1}, [%2];" \
    : "=r"(r0), "=r"(r1) : "r"(a))
#define MMA16816(d, a, b) asm volatile( \
    "mma.sync.aligned.m16n8k16.row.col.f32.bf16.bf16.f32 " \
    "{%0,%1,%2,%3}, {%4,%5,%6,%7}, {%8,%9}, {%0,%1,%2,%3};" \
    : "+f"((d)[0]), "+f"((d)[1]), "+f"((d)[2]), "+f"((d)[3]) \
    : "r"((a)[0]), "r"((a)[1]), "r"((a)[2]), "r"((a)[3]), "r"((b)[0]), "r"((b)[1]))

__device__ __forceinline__ unsigned pack_bf2(float lo, float hi) {
    unsigned r; PACKBF(r, lo, hi); return r;
}

// ---------------- F1: Wx GEMM + fused scores ∥ degree hist ------------------
__global__ __launch_bounds__(256) void k_f1(const float* __restrict__ x,
                                            const float* __restrict__ Ww,
                                            const float* __restrict__ Wb,
                                            const float* __restrict__ aw,
                                            const float* __restrict__ ab,
                                            const int* __restrict__ ei) {
    __shared__ __align__(16) char smbuf[36864];
    __shared__ float biasS[128];
    int tid = threadIdx.x, lane = tid & 31, wid = tid >> 5;

    if (blockIdx.x >= F1_WX) {
        // ---- hist role: 2 edges/thread ----
        int i = (blockIdx.x - F1_WX) * 256 + tid;
        if (i < EE / 2) {
            int2 d2 = *(const int2*)&ei[EE + 2 * i];
            atomicAdd(&g_cnt[clampi(d2.x)], 1);
            atomicAdd(&g_cnt[clampi(d2.y)], 1);
        }
        return;
    }

    __nv_bfloat16* As = (__nv_bfloat16*)smbuf;            // [128][72]
    __nv_bfloat16* Bs = (__nv_bfloat16*)(smbuf + 18432);  // [128][72]
    unsigned short* Cs = (unsigned short*)smbuf;          // overlay
    int n0 = (blockIdx.x >> 1) * 128, c0 = (blockIdx.x & 1) * 128;
    int wm = wid >> 2, wn = wid & 3;
    uint32_t asb = (uint32_t)__cvta_generic_to_shared(As);
    uint32_t bsb = (uint32_t)__cvta_generic_to_shared(Bs);

    if (tid < 128) biasS[tid] = Wb[c0 + tid];

    float acc[4][4][4];
#pragma unroll
    for (int mt = 0; mt < 4; mt++)
#pragma unroll
        for (int nt = 0; nt < 4; nt++)
#pragma unroll
            for (int r = 0; r < 4; r++) acc[mt][nt][r] = 0.f;

    for (int kc = 0; kc < DXX; kc += 64) {
        __syncthreads();
#pragma unroll
        for (int j = 0; j < 8; j++) {
            int lin = tid + 256 * j;
            int row = lin >> 4, q = lin & 15;
            int gn = n0 + row; if (gn >= NN) gn = NN - 1;
            float4 v = *(const float4*)&x[(size_t)gn * DXX + kc + q * 4];
            uint2 o = make_uint2(pack_bf2(v.x, v.y), pack_bf2(v.z, v.w));
            *(uint2*)&As[row * 72 + q * 4] = o;
        }
#pragma unroll
        for (int j = 0; j < 8; j++) {
            int lin = tid + 256 * j;
            int row = lin >> 4, q = lin & 15;
            float4 v = *(const float4*)&Ww[(size_t)(c0 + row) * DXX + kc + q * 4];
            uint2 o = make_uint2(pack_bf2(v.x, v.y), pack_bf2(v.z, v.w));
            *(uint2*)&Bs[row * 72 + q * 4] = o;
        }
        __syncthreads();
#pragma unroll
        for (int ks = 0; ks < 4; ks++) {
            int k0 = ks * 16;
            uint32_t a[4][4], b[4][2];
#pragma unroll
            for (int mt = 0; mt < 4; mt++) {
                uint32_t ad = asb + ((wm * 64 + mt * 16 + (lane & 15)) * 72 +
                                     k0 + (lane >> 4) * 8) * 2;
                LDSM4(a[mt][0], a[mt][1], a[mt][2], a[mt][3], ad);
            }
#pragma unroll
            for (int nt = 0; nt < 4; nt++) {
                uint32_t bd = bsb + ((wn * 32 + nt * 8 + (lane & 7)) * 72 +
                                     k0 + ((lane >> 3) & 1) * 8) * 2;
                LDSM2(b[nt][0], b[nt][1], bd);
            }
#pragma unroll
            for (int mt = 0; mt < 4; mt++)
#pragma unroll
                for (int nt = 0; nt < 4; nt++)
                    MMA16816(acc[mt][nt], a[mt], b[nt]);
        }
    }
    __syncthreads();

    // epilogue: bias + fp8 pack into smem
    int tm = lane >> 2, tp = lane & 3;
#pragma unroll
    for (int mt = 0; mt < 4; mt++)
#pragma unroll
        for (int nt = 0; nt < 4; nt++) {
            int row = wm * 64 + mt * 16 + tm;
            int colp = wn * 16 + nt * 4 + tp;
            int c = colp * 2;
            unsigned short u0, u1;
            PACKF8(u0, acc[mt][nt][0] + biasS[c], acc[mt][nt][1] + biasS[c + 1]);
            PACKF8(u1, acc[mt][nt][2] + biasS[c], acc[mt][nt][3] + biasS[c + 1]);
            Cs[row * 72 + colp] = u0;
            Cs[(row + 8) * 72 + colp] = u1;
        }
    __syncthreads();
    // coalesced fp8 stores
#pragma unroll
    for (int j = 0; j < 4; j++) {
        int lin = tid + 256 * j;
        int row = lin >> 3, q = lin & 7;
        int gn = n0 + row;
        if (gn < NN) {
            uint4 v = *(uint4*)&Cs[row * 72 + q * 8];
            ((uint4*)g_Wxf8)[(size_t)gn * 16 + (c0 >> 4) + q] = v;
        }
    }

    // fused scores: this block holds 2 complete heads (cols c0..c0+127).
    {
        int row = tid & 127, hh = tid >> 7;
        int head = (c0 >> 6) + hh;
        int gn = n0 + row;
        if (gn < NN) {
            const unsigned short* cr = &Cs[row * 72 + hh * 32];
            const float* ai = aw + head * 128;
            const float* aj = ai + 64;
            float va = 0.f, vb = 0.f;
#pragma unroll
            for (int q = 0; q < 32; q++) {
                unsigned r; UNPF8(r, cr[q]);
                float2 f = __half22float2(*(__half2*)&r);
                va += f.x * ai[2 * q] + f.y * ai[2 * q + 1];
                vb += f.x * aj[2 * q] + f.y * aj[2 * q + 1];
            }
            g_sif[gn * 4 + head] = (va + ab[head]) * LOG2E;
            g_sjf[gn * 4 + head] = vb * LOG2E;
        }
    }
}

// ---------------- F2: fused scan (decoupled lookback) + scatter -------------
__global__ __launch_bounds__(256) void k_f2(const int* __restrict__ ei) {
    int tid = threadIdx.x;
    if (blockIdx.x < F2_SCAN) {
        // ---- scan role: 1024 elements per block, 4 per thread ----
        __shared__ int wsum[8];
        __shared__ int s_part[2];
        int b = blockIdx.x;
        int lane = tid & 31, wid = tid >> 5;
        int base = b * 1024 + tid * 4;
        if (b == 0) g_colsum[tid] = 0.f;            // reset for this run

        int v0 = 1, v1 = 1, v2 = 1, v3 = 1;          // +1 self-loop each
        if (base < NN) {
            int4 vv = *(int4*)&g_cnt[base];
            *(int4*)&g_cnt[base] = make_int4(0, 0, 0, 0);
            v0 += vv.x; v1 += vv.y; v2 += vv.z; v3 += vv.w;
        } else { v0 = v1 = v2 = v3 = 0; }
        int t = v0 + v1 + v2 + v3;

        int sc = t;
#pragma unroll
        for (int o = 1; o < 32; o <<= 1) {
            int u = __shfl_up_sync(0xffffffffu, sc, o);
            if (lane >= o) sc += u;
        }
        if (lane == 31) wsum[wid] = sc;
        __syncthreads();
        if (wid == 0 && lane < 8) {
            int ws = wsum[lane];
#pragma unroll
            for (int o = 1; o < 8; o <<= 1) {
                int u = __shfl_up_sync(0xffu, ws, o);
                if (lane >= o) ws += u;
            }
            wsum[lane] = ws;
        }
        __syncthreads();
        int incl = sc + (wid > 0 ? wsum[wid - 1] : 0);
        // publish block aggregate (single packed word)
        if (tid == 255) {
            unsigned pk = 0x80000000u | (unsigned)incl;
            asm volatile("st.release.gpu.u32 [%0], %1;" :: "l"(&g_bstat[b]), "r"(pk));
        }
        // parallel lookback: sum predecessor aggregates
        int val = 0;
        if (tid < b) {
            volatile unsigned* bs = g_bstat;
            unsigned w;
            do { w = bs[tid]; } while (!(w & 0x80000000u));
            val = (int)(w & 0x7fffffffu);
        }
        if (tid < 64) {
#pragma unroll
            for (int o = 16; o; o >>= 1) val += __shfl_xor_sync(0xffffffffu, val, o);
            if ((tid & 31) == 0) s_part[tid >> 5] = val;
        }
        __syncthreads();
        int offset = s_part[0] + s_part[1];
        if (base < NN) {
            int pre = offset + incl - t;
            int a1 = pre + v0, a2 = a1 + v1, a3 = a2 + v2, a4 = a3 + v3;
            g_rowptr[base + 1] = a1;
            g_rowptr[base + 2] = a2;
            g_rowptr[base + 3] = a3;
            g_rowptr[base + 4] = a4;
            *(int4*)&g_cur[base] = make_int4(pre, a1, a2, a3);
        }
        if (b == 0 && tid == 0) g_rowptr[0] = 0;
        __syncthreads();
        __threadfence();
        if (tid == 0) atomicAdd(&g_done, 1);
        return;
    }
    // ---- scatter role: wait for scan completion, then scatter ----
    if (tid == 0) {
        while (ld_acq(&g_done) < F2_SCAN) __nanosleep(128);
    }
    __syncthreads();
    int i = (blockIdx.x - F2_SCAN) * 256 + tid;
    if (i < EE / 2) {
        int2 s2 = *(const int2*)&ei[2 * i];
        int2 d2 = *(const int2*)&ei[EE + 2 * i];
        int pa = atomicAdd(&g_cur[clampi(d2.x)], 1);
        int pb = atomicAdd(&g_cur[clampi(d2.y)], 1);
        if (pa < ETOT) g_csr[pa] = clampi(s2.x);
        if (pb < ETOT) g_csr[pb] = clampi(s2.y);
    } else {
        int n = i - EE / 2;
        if (n < NN) {
            int pos = atomicAdd(&g_cur[n], 1);
            if (pos < ETOT) g_csr[pos] = n;
        }
    }
}

// ---------------- K6: edge softmax + fp8 gather + fused colsum -------------
// Grid exactly NN/8 blocks x 8 warps: every warp owns one node. Column sums
// reduced block-wise in smem, one REDG per column per block.
__global__ __launch_bounds__(256) void k_agg() {
    __shared__ float scol[8][256];
    // reset lookback state for the next replay (f2 of this replay is done)
    if (blockIdx.x == 0) {
        if (threadIdx.x < F2_SCAN) g_bstat[threadIdx.x] = 0u;
        if (threadIdx.x == 63) g_done = 0;
    }
    int wid = threadIdx.x >> 5;
    int n = (blockIdx.x << 3) + wid;           // always < NN (6250*8 == NN)
    int lane = threadIdx.x & 31;
    int h = lane >> 3;
    int s = g_rowptr[n], en = g_rowptr[n + 1];
    float si = g_sif[n * 4 + h];

    __half2 acc0 = __float2half2_rn(0.f), acc1 = acc0, acc2 = acc0, acc3 = acc0;
    float den = 0.f;

    int srcA = g_csr[s];
    int srcB = (s + 1 < en) ? g_csr[s + 1] : srcA;
    float sjA = g_sjf[srcA * 4 + h], sjB = g_sjf[srcB * 4 + h];
    uint2 uA = g_Wxf8[(size_t)srcA * 32 + lane];
    uint2 uB = g_Wxf8[(size_t)srcB * 32 + lane];

    for (int e = s; e < en; e += 2) {
        int nA = (e + 2 < en) ? g_csr[e + 2] : srcA;
        int nB = (e + 3 < en) ? g_csr[e + 3] : srcA;
        float sjAn = g_sjf[nA * 4 + h];
        uint2 uAn = g_Wxf8[(size_t)nA * 32 + lane];
        float sjBn = g_sjf[nB * 4 + h];
        uint2 uBn = g_Wxf8[(size_t)nB * 32 + lane];

        {
            float t = si + sjA;
            t = fmaxf(t, NEG * t);
            float c; EX2A(c, t);
            den += c;
            __half2 ch = __float2half2_rn(c);
            __half2 w0, w1, w2, w3;
            f8_to_f16x2(uA.x, w0, w1);
            f8_to_f16x2(uA.y, w2, w3);
            acc0 = __hfma2(ch, w0, acc0);
            acc1 = __hfma2(ch, w1, acc1);
            acc2 = __hfma2(ch, w2, acc2);
            acc3 = __hfma2(ch, w3, acc3);
        }
        if (e + 1 < en) {
            float t = si + sjB;
            t = fmaxf(t, NEG * t);
            float c; EX2A(c, t);
            den += c;
            __half2 ch = __float2half2_rn(c);
            __half2 w0, w1, w2, w3;
            f8_to_f16x2(uB.x, w0, w1);
            f8_to_f16x2(uB.y, w2, w3);
            acc0 = __hfma2(ch, w0, acc0);
            acc1 = __hfma2(ch, w1, acc1);
            acc2 = __hfma2(ch, w2, acc2);
            acc3 = __hfma2(ch, w3, acc3);
        }
        sjA = sjAn; uA = uAn; sjB = sjBn; uB = uBn;
    }
    float inv = 1.f / den;
    float2 f0 = __half22float2(acc0);
    float2 f1 = __half22float2(acc1);
    float2 f2 = __half22float2(acc2);
    float2 f3 = __half22float2(acc3);
    float e0, e1, e2, e3, e4, e5, e6, e7;
    EX2A(e0, f0.x * inv * LOG2E); EX2A(e1, f0.y * inv * LOG2E);
    EX2A(e2, f1.x * inv * LOG2E); EX2A(e3, f1.y * inv * LOG2E);
    EX2A(e4, f2.x * inv * LOG2E); EX2A(e5, f2.y * inv * LOG2E);
    EX2A(e6, f3.x * inv * LOG2E); EX2A(e7, f3.y * inv * LOG2E);
    unsigned p0, p1, p2, p3;
    PACKBF(p0, e0, e1);
    PACKBF(p1, e2, e3);
    PACKBF(p2, e4, e5);
    PACKBF(p3, e6, e7);
    g_aggh4[(size_t)n * 32 + lane] = make_uint4(p0, p1, p2, p3);

    // fused column sums: lane owns columns lane*8 .. lane*8+7
    float* sc = &scol[wid][lane * 8];
    sc[0] = e0; sc[1] = e1; sc[2] = e2; sc[3] = e3;
    sc[4] = e4; sc[5] = e5; sc[6] = e6; sc[7] = e7;
    __syncthreads();
    int c = threadIdx.x;
    float t = scol[0][c] + scol[1][c] + scol[2][c] + scol[3][c] +
              scol[4][c] + scol[5][c] + scol[6][c] + scol[7][c];
    atomicAdd(&g_colsum[c], t);
}

// ---------------- K8: out = (E*siv) @ Wo^T + b  (bf16 mma.sync) ------------
__global__ __launch_bounds__(256) void k_out(const float* __restrict__ Wo,
                                             const float* __restrict__ Wob,
                                             float* __restrict__ out) {
    __shared__ __align__(16) char smbuf[34816];
    __shared__ float sivS[CC];
    __nv_bfloat16* As = (__nv_bfloat16*)smbuf;            // [128][72]
    __nv_bfloat16* Bs = (__nv_bfloat16*)(smbuf + 18432);  // [64][72]
    float* Csf = (float*)smbuf;                           // overlay
    int tid = threadIdx.x, lane = tid & 31, wid = tid >> 5;
    int n0 = blockIdx.x * 128;
    int wm = wid & 3, wn = wid >> 2;
    uint32_t asb = (uint32_t)__cvta_generic_to_shared(As);
    uint32_t bsb = (uint32_t)__cvta_generic_to_shared(Bs);

    sivS[tid] = 1.f / g_colsum[tid];

    float acc[2][4][4];
#pragma unroll
    for (int mt = 0; mt < 2; mt++)
#pragma unroll
        for (int nt = 0; nt < 4; nt++)
#pragma unroll
            for (int r = 0; r < 4; r++) acc[mt][nt][r] = 0.f;

    for (int cb = 0; cb < CC; cb += 64) {
        __syncthreads();
#pragma unroll
        for (int j = 0; j < 4; j++) {
            int lin = tid + 256 * j;
            int row = lin >> 3, q = lin & 7;
            int gn = n0 + row; if (gn >= NN) gn = NN - 1;
            uint4 u = g_aggh4[(size_t)gn * 32 + (cb >> 3) + q];
            unsigned ua[4] = {u.x, u.y, u.z, u.w};
            unsigned ou[4];
#pragma unroll
            for (int i = 0; i < 4; i++) {
                int c = cb + q * 8 + 2 * i;
                ou[i] = pack_bf2(bflo(ua[i]) * sivS[c], bfhi(ua[i]) * sivS[c + 1]);
            }
            *(uint4*)&As[row * 72 + q * 8] = make_uint4(ou[0], ou[1], ou[2], ou[3]);
        }
#pragma unroll
        for (int j = 0; j < 4; j++) {
            int lin = tid + 256 * j;
            int row = lin >> 4, q = lin & 15;
            float4 v = *(const float4*)&Wo[(size_t)row * CC + cb + q * 4];
            uint2 o = make_uint2(pack_bf2(v.x, v.y), pack_bf2(v.z, v.w));
            *(uint2*)&Bs[row * 72 + q * 4] = o;
        }
        __syncthreads();
#pragma unroll
        for (int ks = 0; ks < 4; ks++) {
            int k0 = ks * 16;
            uint32_t a[2][4], b[4][2];
#pragma unroll
            for (int mt = 0; mt < 2; mt++) {
                uint32_t ad = asb + ((wm * 32 + mt * 16 + (lane & 15)) * 72 +
                                     k0 + (lane >> 4) * 8) * 2;
                LDSM4(a[mt][0], a[mt][1], a[mt][2], a[mt][3], ad);
            }
#pragma unroll
            for (int nt = 0; nt < 4; nt++) {
                uint32_t bd = bsb + ((wn * 32 + nt * 8 + (lane & 7)) * 72 +
                                     k0 + ((lane >> 3) & 1) * 8) * 2;
                LDSM2(b[nt][0], b[nt][1], bd);
            }
#pragma unroll
            for (int mt = 0; mt < 2; mt++)
#pragma unroll
                for (int nt = 0; nt < 4; nt++)
                    MMA16816(acc[mt][nt], a[mt], b[nt]);
        }
    }
    __syncthreads();

    int tm = lane >> 2, tp = lane & 3;
#pragma unroll
    for (int mt = 0; mt < 2; mt++)
#pragma unroll
        for (int nt = 0; nt < 4; nt++) {
            int row = wm * 32 + mt * 16 + tm;
            int col = wn * 32 + nt * 8 + 2 * tp;
            Csf[row * 68 + col] = acc[mt][nt][0];
            Csf[row * 68 + col + 1] = acc[mt][nt][1];
            Csf[(row + 8) * 68 + col] = acc[mt][nt][2];
            Csf[(row + 8) * 68 + col + 1] = acc[mt][nt][3];
        }
    __syncthreads();
#pragma unroll
    for (int j = 0; j < 8; j++) {
        int lin = tid + 256 * j;
        int row = lin >> 4, q = lin & 15;
        int gn = n0 + row;
        if (gn < NN) {
            float4 v = *(float4*)&Csf[row * 68 + q * 4];
            float4 b = *(const float4*)&Wob[q * 4];
            float4 o = {v.x + b.x, v.y + b.y, v.z + b.z, v.w + b.w};
            *(float4*)&out[(size_t)gn * 64 + q * 4] = o;
        }
    }
}

// ---------------- launch ----------------------------------------------------
extern "C" void kernel_launch(void* const* d_in, const int* in_sizes, int n_in,
                              void* d_out, int out_size) {
    (void)out_size;
    const void* p[8];
    for (int j = 0; j < 8; j++) p[j] = (j < n_in) ? d_in[j] : 0;
    const int want[8] = {2 * EE, NN * DXX, KH * DHH * DXX, KH * DHH,
                         KH * 2 * DHH, KH, DHH * CC, DHH};
    for (int j = 0; j < 8; j++)
        for (int i = 0; i < n_in; i++)
            if (in_sizes[i] == want[j]) { p[j] = d_in[i]; break; }

    const int*   ei  = (const int*)p[0];
    const float* x   = (const float*)p[1];
    const float* Ww  = (const float*)p[2];
    const float* Wb  = (const float*)p[3];
    const float* aw  = (const float*)p[4];
    const float* ab  = (const float*)p[5];
    const float* Wo  = (const float*)p[6];
    const float* Wob = (const float*)p[7];
    float* out = (float*)d_out;

    k_f1<<<F1_WX + F1_HIST, 256>>>(x, Ww, Wb, aw, ab, ei);
    k_f2<<<F2_SCAN + F2_SCAT, 256>>>(ei);
    k_agg<<<NN / 8, 256>>>();
    k_out<<<391, 256>>>(Wo, Wob, out);
}